// round 12
// baseline (speedup 1.0000x reference)
#include <cuda_runtime.h>
#include <cuda_bf16.h>
#include <cstdint>

// Problem constants
#define N_TOT 4096
#define D1    4096
#define D2    2048
#define NTI   16            // 256-row blocks
#define NTJ   32            // 128-col blocks
#define NTILES 272          // tiles (I,J) with J >= 2I
#define BK    64            // k-tile

// SMEM: 4 stages A (4x32KB) | 4 stages B (4x16KB) | reduction scratch
#define SM_ASTAGE 32768
#define SM_BSTAGE 16384
#define SM_B_OFF  131072
#define SM_RED    196608
#define SMEM_TOTAL (196608 + 2048)

// ---------------- device scratch ----------------
__device__ __nv_bfloat16 g_t1[(size_t)N_TOT * D1];   // 32 MB
__device__ __nv_bfloat16 g_t2[(size_t)N_TOT * D2];   // 16 MB
__device__ float g_sq1[N_TOT];
__device__ float g_sq2[N_TOT];
__device__ float g_pcs1[(size_t)256 * D1];           // 4 MB
__device__ float g_pcs2[(size_t)256 * D2];           // 2 MB
__device__ float g_colsum1[D1];
__device__ float g_colsum2[D2];
__device__ float g_c[2];
__device__ float g_partials[NTILES];
__device__ int   g_ctr = 0;
__device__ float g_kk[(size_t)NTILES * 32768];       // 35.7 MB k1 scratch

// ---------------- helpers ----------------
__device__ __forceinline__ float ex2f(float x) {
    float y; asm("ex2.approx.ftz.f32 %0, %1;" : "=f"(y) : "f"(x)); return y;
}
// sum_{i=0..4} exp(-t/2^i) = y + y^2 + y^4 + y^8 + y^16, y = exp(-t/16)
__device__ __forceinline__ float kern5b(float l2, float c16) {
    float y = ex2f(-fmaxf(l2, 0.0f) * c16);
    float y2 = y * y, y4 = y2 * y2, y8 = y4 * y4, y16 = y8 * y8;
    return y + y2 + y4 + y8 + y16;
}
__device__ __forceinline__ void cpa16(uint32_t s, const void* g) {
    asm volatile("cp.async.cg.shared.global [%0], [%1], 16;" :: "r"(s), "l"(g));
}
__device__ __forceinline__ void ldsm4(uint32_t* r, uint32_t addr) {
    asm volatile("ldmatrix.sync.aligned.m8n8.x4.shared.b16 {%0,%1,%2,%3}, [%4];"
        : "=r"(r[0]), "=r"(r[1]), "=r"(r[2]), "=r"(r[3]) : "r"(addr));
}
__device__ __forceinline__ void mma16816(float* d, const uint32_t* a, const uint32_t* b) {
    asm volatile(
        "mma.sync.aligned.m16n8k16.row.col.f32.bf16.bf16.f32 "
        "{%0,%1,%2,%3}, {%4,%5,%6,%7}, {%8,%9}, {%0,%1,%2,%3};"
        : "+f"(d[0]), "+f"(d[1]), "+f"(d[2]), "+f"(d[3])
        : "r"(a[0]), "r"(a[1]), "r"(a[2]), "r"(a[3]), "r"(b[0]), "r"(b[1]));
}

// ---------------- pre-pass 1: convert + row sq-norms + col partial sums ----------------
__global__ void kprep(const float* __restrict__ z1s, const float* __restrict__ z1t,
                      const float* __restrict__ z2s, const float* __restrict__ z2t) {
    int bid = blockIdx.x, tid = threadIdx.x;
    int lane = tid & 31, wid = tid >> 5;
    __shared__ float sred1[16][8];
    __shared__ float sred2[16][8];
    float4 ca1[4], ca2[2];
    #pragma unroll
    for (int s = 0; s < 4; s++) ca1[s] = make_float4(0.f, 0.f, 0.f, 0.f);
    #pragma unroll
    for (int s = 0; s < 2; s++) ca2[s] = make_float4(0.f, 0.f, 0.f, 0.f);

    for (int r16 = 0; r16 < 16; r16++) {
        int r = bid * 16 + r16;
        const float4* s1 = (const float4*)((r < 2048) ? z1s + (size_t)r * D1
                                                      : z1t + (size_t)(r - 2048) * D1);
        float sq = 0.0f;
        #pragma unroll
        for (int s = 0; s < 4; s++) {
            float4 v = s1[tid + 256 * s];
            __nv_bfloat162 h0 = {__float2bfloat16(v.x), __float2bfloat16(v.y)};
            __nv_bfloat162 h1 = {__float2bfloat16(v.z), __float2bfloat16(v.w)};
            uint2 pk = {*(uint32_t*)&h0, *(uint32_t*)&h1};
            *(uint2*)(g_t1 + (size_t)r * D1 + 4 * (tid + 256 * s)) = pk;
            sq += v.x * v.x + v.y * v.y + v.z * v.z + v.w * v.w;
            ca1[s].x += v.x; ca1[s].y += v.y; ca1[s].z += v.z; ca1[s].w += v.w;
        }
        #pragma unroll
        for (int o = 16; o; o >>= 1) sq += __shfl_xor_sync(0xffffffffu, sq, o);
        if (lane == 0) sred1[r16][wid] = sq;

        const float4* s2 = (const float4*)((r < 2048) ? z2s + (size_t)r * D2
                                                      : z2t + (size_t)(r - 2048) * D2);
        sq = 0.0f;
        #pragma unroll
        for (int s = 0; s < 2; s++) {
            float4 v = s2[tid + 256 * s];
            __nv_bfloat162 h0 = {__float2bfloat16(v.x), __float2bfloat16(v.y)};
            __nv_bfloat162 h1 = {__float2bfloat16(v.z), __float2bfloat16(v.w)};
            uint2 pk = {*(uint32_t*)&h0, *(uint32_t*)&h1};
            *(uint2*)(g_t2 + (size_t)r * D2 + 4 * (tid + 256 * s)) = pk;
            sq += v.x * v.x + v.y * v.y + v.z * v.z + v.w * v.w;
            ca2[s].x += v.x; ca2[s].y += v.y; ca2[s].z += v.z; ca2[s].w += v.w;
        }
        #pragma unroll
        for (int o = 16; o; o >>= 1) sq += __shfl_xor_sync(0xffffffffu, sq, o);
        if (lane == 0) sred2[r16][wid] = sq;
    }
    #pragma unroll
    for (int s = 0; s < 4; s++)
        *(float4*)&g_pcs1[(size_t)bid * D1 + 1024 * s + 4 * tid] = ca1[s];
    #pragma unroll
    for (int s = 0; s < 2; s++)
        *(float4*)&g_pcs2[(size_t)bid * D2 + 1024 * s + 4 * tid] = ca2[s];
    __syncthreads();
    if (tid < 16) {
        float s = 0.0f;
        #pragma unroll
        for (int w = 0; w < 8; w++) s += sred1[tid][w];
        g_sq1[bid * 16 + tid] = s;
    } else if (tid < 32) {
        float s = 0.0f;
        #pragma unroll
        for (int w = 0; w < 8; w++) s += sred2[tid - 16][w];
        g_sq2[bid * 16 + tid - 16] = s;
    }
}

// ---------------- pre-pass 2: reduce col partial sums ----------------
__global__ void kcol2() {
    int tid = threadIdx.x;
    if (blockIdx.x < 16) {
        int j = blockIdx.x * 256 + tid;
        float s = 0.0f;
        #pragma unroll 4
        for (int k = 0; k < 256; k++) s += g_pcs1[(size_t)k * D1 + j];
        g_colsum1[j] = s;
    } else {
        int j = (blockIdx.x - 16) * 256 + tid;
        float s = 0.0f;
        #pragma unroll 4
        for (int k = 0; k < 256; k++) s += g_pcs2[(size_t)k * D2 + j];
        g_colsum2[j] = s;
    }
}

// ---------------- pre-pass 3: bandwidth constants ----------------
__global__ void kconst() {
    int tid = threadIdx.x;
    __shared__ double sh[512];

    double ssq = 0.0, ss = 0.0;
    for (int j = tid; j < D1; j += 256) { double v = (double)g_colsum1[j]; ss += v * v; }
    for (int j = tid; j < N_TOT; j += 256) ssq += (double)g_sq1[j];
    sh[tid] = ssq; sh[256 + tid] = ss; __syncthreads();
    for (int s = 128; s; s >>= 1) {
        if (tid < s) { sh[tid] += sh[tid + s]; sh[256 + tid] += sh[256 + tid + s]; }
        __syncthreads();
    }
    if (tid == 0) {
        double n = (double)N_TOT;
        double suml2 = 2.0 * n * sh[0] - 2.0 * sh[256];
        double bw = suml2 / (n * n - n) / 4.0;
        g_c[0] = (float)(1.4426950408889634 / bw);
    }
    __syncthreads();

    ssq = 0.0; ss = 0.0;
    for (int j = tid; j < D2; j += 256) { double v = (double)g_colsum2[j]; ss += v * v; }
    for (int j = tid; j < N_TOT; j += 256) ssq += (double)g_sq2[j];
    sh[tid] = ssq; sh[256 + tid] = ss; __syncthreads();
    for (int s = 128; s; s >>= 1) {
        if (tid < s) { sh[tid] += sh[tid + s]; sh[256 + tid] += sh[256 + tid + s]; }
        __syncthreads();
    }
    if (tid == 0) {
        double n = (double)N_TOT;
        double suml2 = 2.0 * n * sh[0] - 2.0 * sh[256];
        double bw = suml2 / (n * n - n) / 4.0;
        g_c[1] = (float)(1.4426950408889634 / bw);
    }
}

// ---------------- main fused kernel: 256x128 CTA, 16 warps, 64x32 warp tiles ----------------
__device__ __forceinline__ void load_tiles(uint32_t sb, int stage,
        const __nv_bfloat16* A, const __nv_bfloat16* B, int ld, int k0, int tid) {
    uint32_t sA = sb + (uint32_t)stage * SM_ASTAGE;
    uint32_t sB = sb + SM_B_OFF + (uint32_t)stage * SM_BSTAGE;
    #pragma unroll
    for (int v = 0; v < 4; v++) {               // A: 256x64 = 2048 x 16B
        int chunk = tid + v * 512;
        int row = chunk >> 3, c = chunk & 7;
        uint32_t off = (uint32_t)(row * 128 + ((c ^ (row & 7)) << 4));   // SW128
        cpa16(sA + off, A + (size_t)row * ld + k0 + c * 8);
    }
    #pragma unroll
    for (int v = 0; v < 2; v++) {               // B: 128x64 = 1024 x 16B
        int chunk = tid + v * 512;
        int row = chunk >> 3, c = chunk & 7;
        uint32_t off = (uint32_t)(row * 128 + ((c ^ (row & 7)) << 4));
        cpa16(sB + off, B + (size_t)row * ld + k0 + c * 8);
    }
}

__device__ __forceinline__ void compute_stage(uint32_t sA, uint32_t sB,
        float acc[4][4][4], int lane, int wm, int wn) {
    #pragma unroll
    for (int s16 = 0; s16 < 4; s16++) {
        uint32_t a[4][4], b[2][4];
        #pragma unroll
        for (int mt = 0; mt < 4; mt++) {
            int row = wm * 64 + mt * 16 + (lane & 15);
            int ch  = 2 * s16 + (lane >> 4);
            ldsm4(a[mt], sA + (uint32_t)(row * 128 + ((ch ^ (row & 7)) << 4)));
        }
        #pragma unroll
        for (int p = 0; p < 2; p++) {
            int g = lane >> 3;
            int row = wn * 32 + p * 16 + ((g >> 1) << 3) + (lane & 7);
            int ch  = 2 * s16 + (g & 1);
            ldsm4(b[p], sB + (uint32_t)(row * 128 + ((ch ^ (row & 7)) << 4)));
        }
        #pragma unroll
        for (int mt = 0; mt < 4; mt++)
            #pragma unroll
            for (int nt = 0; nt < 4; nt++)
                mma16816(acc[mt][nt], a[mt], &b[nt >> 1][(nt & 1) * 2]);
    }
}

__device__ void run_gemm(const __nv_bfloat16* A, const __nv_bfloat16* B, int ld,
        int nsteps, float acc[4][4][4], uint32_t sb, int tid, int lane, int wm, int wn) {
    asm volatile("cp.async.wait_group 0;");     // prior phase fully drained
    __syncthreads();
    #pragma unroll
    for (int s = 0; s < 3; s++) {
        load_tiles(sb, s, A, B, ld, s * BK, tid);
        asm volatile("cp.async.commit_group;");
    }
    for (int s = 0; s < nsteps; s++) {
        asm volatile("cp.async.wait_group 2;");
        __syncthreads();
        if (s + 3 < nsteps)
            load_tiles(sb, (s + 3) & 3, A, B, ld, (s + 3) * BK, tid);
        asm volatile("cp.async.commit_group;");
        compute_stage(sb + (uint32_t)(s & 3) * SM_ASTAGE,
                      sb + SM_B_OFF + (uint32_t)(s & 3) * SM_BSTAGE,
                      acc, lane, wm, wn);
    }
}

__global__ __launch_bounds__(512, 1) void kmain(float* out) {
    extern __shared__ __align__(16) char smem[];
    uint32_t sb = (uint32_t)__cvta_generic_to_shared(smem);
    int tid = threadIdx.x, lane = tid & 31, wid = tid >> 5;
    int wm = wid >> 2, wn = wid & 3;    // 4 x 4 warp grid, warp tile 64x32

    // tile mapping: (I,J), I in [0,16), J in [2I, 32)
    int rem = blockIdx.x, I = 0;
    while (rem >= NTJ - 2 * I) { rem -= NTJ - 2 * I; I++; }
    int J = 2 * I + rem;

    float acc[4][4][4];
    #pragma unroll
    for (int mt = 0; mt < 4; mt++)
        #pragma unroll
        for (int nt = 0; nt < 4; nt++)
            #pragma unroll
            for (int r = 0; r < 4; r++) acc[mt][nt][r] = 0.0f;

    // ---- phase 1: G1 over total1 ----
    run_gemm(g_t1 + (size_t)(I * 256) * D1, g_t1 + (size_t)(J * 128) * D1,
             D1, D1 / BK, acc, sb, tid, lane, wm, wn);

    {
        float c116 = g_c[0] * 0.0625f;
        float sqi[4][2], sqj[4][2];
        #pragma unroll
        for (int mt = 0; mt < 4; mt++) {
            int ib = I * 256 + wm * 64 + mt * 16 + (lane >> 2);
            sqi[mt][0] = g_sq1[ib];
            sqi[mt][1] = g_sq1[ib + 8];
        }
        #pragma unroll
        for (int nt = 0; nt < 4; nt++) {
            int jb = J * 128 + wn * 32 + nt * 8 + ((lane & 3) << 1);
            sqj[nt][0] = g_sq1[jb];
            sqj[nt][1] = g_sq1[jb + 1];
        }
        float* kkb = g_kk + (size_t)blockIdx.x * 32768 + tid * 64;
        #pragma unroll
        for (int mt = 0; mt < 4; mt++)
            #pragma unroll
            for (int nt = 0; nt < 4; nt++) {
                float4 kv;
                float* kp = (float*)&kv;
                #pragma unroll
                for (int r = 0; r < 4; r++) {
                    float l2 = sqi[mt][r >> 1] + sqj[nt][r & 1] - 2.0f * acc[mt][nt][r];
                    kp[r] = kern5b(l2, c116);
                    acc[mt][nt][r] = 0.0f;
                }
                *(float4*)(kkb + mt * 16 + nt * 4) = kv;
            }
    }

    // ---- phase 2: G2 over total2 ----
    run_gemm(g_t2 + (size_t)(I * 256) * D2, g_t2 + (size_t)(J * 128) * D2,
             D2, D2 / BK, acc, sb, tid, lane, wm, wn);

    float part = 0.0f;
    {
        float c216 = g_c[1] * 0.0625f;
        float sqi[4][2], sqj[4][2];
        #pragma unroll
        for (int mt = 0; mt < 4; mt++) {
            int ib = I * 256 + wm * 64 + mt * 16 + (lane >> 2);
            sqi[mt][0] = g_sq2[ib];
            sqi[mt][1] = g_sq2[ib + 8];
        }
        #pragma unroll
        for (int nt = 0; nt < 4; nt++) {
            int jb = J * 128 + wn * 32 + nt * 8 + ((lane & 3) << 1);
            sqj[nt][0] = g_sq2[jb];
            sqj[nt][1] = g_sq2[jb + 1];
        }
        const float PC = 1.0f / (2048.0f * 2047.0f);
        const float QC = 1.0f / (2048.0f * 2048.0f);
        const float* kkb = g_kk + (size_t)blockIdx.x * 32768 + tid * 64;
        #pragma unroll
        for (int mt = 0; mt < 4; mt++)
            #pragma unroll
            for (int nt = 0; nt < 4; nt++) {
                float4 kv = *(const float4*)(kkb + mt * 16 + nt * 4);
                const float* kp = (const float*)&kv;
                #pragma unroll
                for (int r = 0; r < 4; r++) {
                    int i = I * 256 + wm * 64 + mt * 16 + (lane >> 2) + ((r >> 1) << 3);
                    int j = J * 128 + wn * 32 + nt * 8 + ((lane & 3) << 1) + (r & 1);
                    float l2 = sqi[mt][r >> 1] + sqj[nt][r & 1] - 2.0f * acc[mt][nt][r];
                    float k2v = kern5b(l2, c216);
                    // strictly-upper mask, x2 symmetry, +/- index-matrix coefficient
                    float coef = (i < j) ? 2.0f * (((i >> 11) == (j >> 11)) ? PC : -QC)
                                         : 0.0f;
                    part += kp[r] * k2v * coef;
                }
            }
    }

    // deterministic CTA reduction
    #pragma unroll
    for (int o = 16; o; o >>= 1) part += __shfl_xor_sync(0xffffffffu, part, o);
    float* red = (float*)(smem + SM_RED);
    __syncthreads();
    if (lane == 0) red[wid] = part;
    __syncthreads();
    __shared__ int s_last;
    if (tid == 0) {
        float s = 0.0f;
        #pragma unroll
        for (int w = 0; w < 16; w++) s += red[w];
        g_partials[blockIdx.x] = s;
        __threadfence();
        int old = atomicAdd(&g_ctr, 1);
        s_last = (old == NTILES - 1) ? 1 : 0;
    }
    __syncthreads();

    // last CTA: deterministic final reduction (fixed-order tree), reset counter
    if (s_last) {
        __threadfence();
        double* shd = (double*)(smem + SM_RED);
        double a = 0.0;
        if (tid < 256) {
            a = (double)g_partials[tid];
            if (tid + 256 < NTILES) a += (double)g_partials[tid + 256];
            shd[tid] = a;
        }
        __syncthreads();
        for (int s = 128; s; s >>= 1) {
            if (tid < s) shd[tid] += shd[tid + s];
            __syncthreads();
        }
        if (tid == 0) {
            out[0] = (float)(shd[0] + 2.0 / 2047.0);
            g_ctr = 0;                       // reset for next graph replay
        }
    }
}

// ---------------- launch ----------------
extern "C" void kernel_launch(void* const* d_in, const int* in_sizes, int n_in,
                              void* d_out, int out_size) {
    const float* z1s = (const float*)d_in[0];
    const float* z1t = (const float*)d_in[1];
    const float* z2s = (const float*)d_in[2];
    const float* z2t = (const float*)d_in[3];

    cudaFuncSetAttribute(kmain, cudaFuncAttributeMaxDynamicSharedMemorySize, SMEM_TOTAL);

    kprep<<<256, 256>>>(z1s, z1t, z2s, z2t);
    kcol2<<<24, 256>>>();
    kconst<<<1, 256>>>();
    kmain<<<NTILES, 512, SMEM_TOTAL>>>((float*)d_out);
}

// round 13
// speedup vs baseline: 1.0603x; 1.0603x over previous
#include <cuda_runtime.h>
#include <cuda_bf16.h>
#include <cstdint>

// Problem constants
#define N_TOT 4096
#define D1    4096
#define D2    2048
#define NTI   16            // 256-row blocks
#define NTJ   32            // 128-col blocks
#define NTILES 272          // tiles (I,J) with J >= 2I
#define BK    64            // k-tile

// SMEM: 4 stages A (4x32KB) | 4 stages B (4x16KB) | reduction scratch
#define SM_ASTAGE 32768
#define SM_BSTAGE 16384
#define SM_B_OFF  131072
#define SM_RED    196608
#define SMEM_TOTAL (196608 + 2048)

// ---------------- device scratch ----------------
__device__ __nv_bfloat16 g_t1[(size_t)N_TOT * D1];   // 32 MB
__device__ __nv_bfloat16 g_t2[(size_t)N_TOT * D2];   // 16 MB
__device__ float g_sq1[N_TOT];
__device__ float g_sq2[N_TOT];
__device__ float g_pcs1[(size_t)512 * D1];           // 8 MB
__device__ float g_pcs2[(size_t)512 * D2];           // 4 MB
__device__ float g_colsum1[D1];
__device__ float g_colsum2[D2];
__device__ float g_c[2];
__device__ float g_partials[NTILES];
__device__ int   g_ctr = 0;
__device__ float g_kk[(size_t)NTILES * 32768];       // 35.7 MB k1 scratch

// ---------------- helpers ----------------
__device__ __forceinline__ float ex2f(float x) {
    float y; asm("ex2.approx.ftz.f32 %0, %1;" : "=f"(y) : "f"(x)); return y;
}
// sum_{i=0..4} exp(-t/2^i) = y + y^2 + y^4 + y^8 + y^16, y = exp(-t/16)
__device__ __forceinline__ float kern5b(float l2, float c16) {
    float y = ex2f(-fmaxf(l2, 0.0f) * c16);
    float y2 = y * y, y4 = y2 * y2, y8 = y4 * y4, y16 = y8 * y8;
    return y + y2 + y4 + y8 + y16;
}
__device__ __forceinline__ void cpa16(uint32_t s, const void* g) {
    asm volatile("cp.async.cg.shared.global [%0], [%1], 16;" :: "r"(s), "l"(g));
}
__device__ __forceinline__ void ldsm4(uint32_t* r, uint32_t addr) {
    asm volatile("ldmatrix.sync.aligned.m8n8.x4.shared.b16 {%0,%1,%2,%3}, [%4];"
        : "=r"(r[0]), "=r"(r[1]), "=r"(r[2]), "=r"(r[3]) : "r"(addr));
}
__device__ __forceinline__ void mma16816(float* d, const uint32_t* a, const uint32_t* b) {
    asm volatile(
        "mma.sync.aligned.m16n8k16.row.col.f32.bf16.bf16.f32 "
        "{%0,%1,%2,%3}, {%4,%5,%6,%7}, {%8,%9}, {%0,%1,%2,%3};"
        : "+f"(d[0]), "+f"(d[1]), "+f"(d[2]), "+f"(d[3])
        : "r"(a[0]), "r"(a[1]), "r"(a[2]), "r"(a[3]), "r"(b[0]), "r"(b[1]));
}

// ---------------- pre-pass 1: convert + row sq-norms + col partial sums ----------------
__global__ void kprep(const float* __restrict__ z1s, const float* __restrict__ z1t,
                      const float* __restrict__ z2s, const float* __restrict__ z2t) {
    int bid = blockIdx.x, tid = threadIdx.x;
    int lane = tid & 31, wid = tid >> 5;
    __shared__ float sred1[8][8];
    __shared__ float sred2[8][8];
    float4 ca1[4], ca2[2];
    #pragma unroll
    for (int s = 0; s < 4; s++) ca1[s] = make_float4(0.f, 0.f, 0.f, 0.f);
    #pragma unroll
    for (int s = 0; s < 2; s++) ca2[s] = make_float4(0.f, 0.f, 0.f, 0.f);

    for (int r8 = 0; r8 < 8; r8++) {
        int r = bid * 8 + r8;
        const float4* s1 = (const float4*)((r < 2048) ? z1s + (size_t)r * D1
                                                      : z1t + (size_t)(r - 2048) * D1);
        float sq = 0.0f;
        #pragma unroll
        for (int s = 0; s < 4; s++) {
            float4 v = s1[tid + 256 * s];
            __nv_bfloat162 h0 = {__float2bfloat16(v.x), __float2bfloat16(v.y)};
            __nv_bfloat162 h1 = {__float2bfloat16(v.z), __float2bfloat16(v.w)};
            uint2 pk = {*(uint32_t*)&h0, *(uint32_t*)&h1};
            *(uint2*)(g_t1 + (size_t)r * D1 + 4 * (tid + 256 * s)) = pk;
            sq += v.x * v.x + v.y * v.y + v.z * v.z + v.w * v.w;
            ca1[s].x += v.x; ca1[s].y += v.y; ca1[s].z += v.z; ca1[s].w += v.w;
        }
        #pragma unroll
        for (int o = 16; o; o >>= 1) sq += __shfl_xor_sync(0xffffffffu, sq, o);
        if (lane == 0) sred1[r8][wid] = sq;

        const float4* s2 = (const float4*)((r < 2048) ? z2s + (size_t)r * D2
                                                      : z2t + (size_t)(r - 2048) * D2);
        sq = 0.0f;
        #pragma unroll
        for (int s = 0; s < 2; s++) {
            float4 v = s2[tid + 256 * s];
            __nv_bfloat162 h0 = {__float2bfloat16(v.x), __float2bfloat16(v.y)};
            __nv_bfloat162 h1 = {__float2bfloat16(v.z), __float2bfloat16(v.w)};
            uint2 pk = {*(uint32_t*)&h0, *(uint32_t*)&h1};
            *(uint2*)(g_t2 + (size_t)r * D2 + 4 * (tid + 256 * s)) = pk;
            sq += v.x * v.x + v.y * v.y + v.z * v.z + v.w * v.w;
            ca2[s].x += v.x; ca2[s].y += v.y; ca2[s].z += v.z; ca2[s].w += v.w;
        }
        #pragma unroll
        for (int o = 16; o; o >>= 1) sq += __shfl_xor_sync(0xffffffffu, sq, o);
        if (lane == 0) sred2[r8][wid] = sq;
    }
    #pragma unroll
    for (int s = 0; s < 4; s++)
        *(float4*)&g_pcs1[(size_t)bid * D1 + 1024 * s + 4 * tid] = ca1[s];
    #pragma unroll
    for (int s = 0; s < 2; s++)
        *(float4*)&g_pcs2[(size_t)bid * D2 + 1024 * s + 4 * tid] = ca2[s];
    __syncthreads();
    if (tid < 8) {
        float s = 0.0f;
        #pragma unroll
        for (int w = 0; w < 8; w++) s += sred1[tid][w];
        g_sq1[bid * 8 + tid] = s;
    } else if (tid < 16) {
        float s = 0.0f;
        #pragma unroll
        for (int w = 0; w < 8; w++) s += sred2[tid - 8][w];
        g_sq2[bid * 8 + tid - 8] = s;
    }
}

// ---------------- pre-pass 2: reduce col partial sums ----------------
__global__ void kcol2() {
    int tid = threadIdx.x;
    if (blockIdx.x < 16) {
        int j = blockIdx.x * 256 + tid;
        float s = 0.0f;
        for (int k = 0; k < 512; k++) s += g_pcs1[(size_t)k * D1 + j];
        g_colsum1[j] = s;
    } else {
        int j = (blockIdx.x - 16) * 256 + tid;
        float s = 0.0f;
        for (int k = 0; k < 512; k++) s += g_pcs2[(size_t)k * D2 + j];
        g_colsum2[j] = s;
    }
}

// ---------------- pre-pass 3: bandwidth constants ----------------
__global__ void kconst() {
    int tid = threadIdx.x;
    __shared__ double sh[512];

    double ssq = 0.0, ss = 0.0;
    for (int j = tid; j < D1; j += 256) { double v = (double)g_colsum1[j]; ss += v * v; }
    for (int j = tid; j < N_TOT; j += 256) ssq += (double)g_sq1[j];
    sh[tid] = ssq; sh[256 + tid] = ss; __syncthreads();
    for (int s = 128; s; s >>= 1) {
        if (tid < s) { sh[tid] += sh[tid + s]; sh[256 + tid] += sh[256 + tid + s]; }
        __syncthreads();
    }
    if (tid == 0) {
        double n = (double)N_TOT;
        double suml2 = 2.0 * n * sh[0] - 2.0 * sh[256];
        double bw = suml2 / (n * n - n) / 4.0;
        g_c[0] = (float)(1.4426950408889634 / bw);
    }
    __syncthreads();

    ssq = 0.0; ss = 0.0;
    for (int j = tid; j < D2; j += 256) { double v = (double)g_colsum2[j]; ss += v * v; }
    for (int j = tid; j < N_TOT; j += 256) ssq += (double)g_sq2[j];
    sh[tid] = ssq; sh[256 + tid] = ss; __syncthreads();
    for (int s = 128; s; s >>= 1) {
        if (tid < s) { sh[tid] += sh[tid + s]; sh[256 + tid] += sh[256 + tid + s]; }
        __syncthreads();
    }
    if (tid == 0) {
        double n = (double)N_TOT;
        double suml2 = 2.0 * n * sh[0] - 2.0 * sh[256];
        double bw = suml2 / (n * n - n) / 4.0;
        g_c[1] = (float)(1.4426950408889634 / bw);
    }
}

// ---------------- main fused kernel: 256x128 CTA, 16 warps, 64x32 warp tiles ----------------
__device__ __forceinline__ void load_tiles(uint32_t sb, int stage,
        const __nv_bfloat16* A, const __nv_bfloat16* B, int ld, int k0, int tid) {
    uint32_t sA = sb + (uint32_t)stage * SM_ASTAGE;
    uint32_t sB = sb + SM_B_OFF + (uint32_t)stage * SM_BSTAGE;
    #pragma unroll
    for (int v = 0; v < 4; v++) {               // A: 256x64 = 2048 x 16B
        int chunk = tid + v * 512;
        int row = chunk >> 3, c = chunk & 7;
        uint32_t off = (uint32_t)(row * 128 + ((c ^ (row & 7)) << 4));   // SW128
        cpa16(sA + off, A + (size_t)row * ld + k0 + c * 8);
    }
    #pragma unroll
    for (int v = 0; v < 2; v++) {               // B: 128x64 = 1024 x 16B
        int chunk = tid + v * 512;
        int row = chunk >> 3, c = chunk & 7;
        uint32_t off = (uint32_t)(row * 128 + ((c ^ (row & 7)) << 4));
        cpa16(sB + off, B + (size_t)row * ld + k0 + c * 8);
    }
}

__device__ __forceinline__ void compute_stage(uint32_t sA, uint32_t sB,
        float acc[4][4][4], int lane, int wm, int wn) {
    #pragma unroll
    for (int s16 = 0; s16 < 4; s16++) {
        uint32_t a[4][4], b[2][4];
        #pragma unroll
        for (int mt = 0; mt < 4; mt++) {
            int row = wm * 64 + mt * 16 + (lane & 15);
            int ch  = 2 * s16 + (lane >> 4);
            ldsm4(a[mt], sA + (uint32_t)(row * 128 + ((ch ^ (row & 7)) << 4)));
        }
        #pragma unroll
        for (int p = 0; p < 2; p++) {
            int g = lane >> 3;
            int row = wn * 32 + p * 16 + ((g >> 1) << 3) + (lane & 7);
            int ch  = 2 * s16 + (g & 1);
            ldsm4(b[p], sB + (uint32_t)(row * 128 + ((ch ^ (row & 7)) << 4)));
        }
        #pragma unroll
        for (int mt = 0; mt < 4; mt++)
            #pragma unroll
            for (int nt = 0; nt < 4; nt++)
                mma16816(acc[mt][nt], a[mt], &b[nt >> 1][(nt & 1) * 2]);
    }
}

__device__ void run_gemm(const __nv_bfloat16* A, const __nv_bfloat16* B, int ld,
        int nsteps, float acc[4][4][4], uint32_t sb, int tid, int lane, int wm, int wn) {
    asm volatile("cp.async.wait_group 0;");     // prior phase fully drained
    __syncthreads();
    #pragma unroll
    for (int s = 0; s < 3; s++) {
        load_tiles(sb, s, A, B, ld, s * BK, tid);
        asm volatile("cp.async.commit_group;");
    }
    for (int s = 0; s < nsteps; s++) {
        asm volatile("cp.async.wait_group 2;");
        __syncthreads();
        if (s + 3 < nsteps)
            load_tiles(sb, (s + 3) & 3, A, B, ld, (s + 3) * BK, tid);
        asm volatile("cp.async.commit_group;");
        compute_stage(sb + (uint32_t)(s & 3) * SM_ASTAGE,
                      sb + SM_B_OFF + (uint32_t)(s & 3) * SM_BSTAGE,
                      acc, lane, wm, wn);
    }
}

__global__ __launch_bounds__(512, 1) void kmain(float* out) {
    extern __shared__ __align__(16) char smem[];
    uint32_t sb = (uint32_t)__cvta_generic_to_shared(smem);
    int tid = threadIdx.x, lane = tid & 31, wid = tid >> 5;
    int wm = wid >> 2, wn = wid & 3;    // 4 x 4 warp grid, warp tile 64x32

    // tile mapping: (I,J), I in [0,16), J in [2I, 32)
    int rem = blockIdx.x, I = 0;
    while (rem >= NTJ - 2 * I) { rem -= NTJ - 2 * I; I++; }
    int J = 2 * I + rem;

    float acc[4][4][4];
    #pragma unroll
    for (int mt = 0; mt < 4; mt++)
        #pragma unroll
        for (int nt = 0; nt < 4; nt++)
            #pragma unroll
            for (int r = 0; r < 4; r++) acc[mt][nt][r] = 0.0f;

    // ---- phase 1: G1 over total1 ----
    run_gemm(g_t1 + (size_t)(I * 256) * D1, g_t1 + (size_t)(J * 128) * D1,
             D1, D1 / BK, acc, sb, tid, lane, wm, wn);

    {
        float c116 = g_c[0] * 0.0625f;
        float sqi[4][2], sqj[4][2];
        #pragma unroll
        for (int mt = 0; mt < 4; mt++) {
            int ib = I * 256 + wm * 64 + mt * 16 + (lane >> 2);
            sqi[mt][0] = g_sq1[ib];
            sqi[mt][1] = g_sq1[ib + 8];
        }
        #pragma unroll
        for (int nt = 0; nt < 4; nt++) {
            int jb = J * 128 + wn * 32 + nt * 8 + ((lane & 3) << 1);
            sqj[nt][0] = g_sq1[jb];
            sqj[nt][1] = g_sq1[jb + 1];
        }
        float* kkb = g_kk + (size_t)blockIdx.x * 32768;
        #pragma unroll
        for (int mt = 0; mt < 4; mt++)
            #pragma unroll
            for (int nt = 0; nt < 4; nt++)
                #pragma unroll
                for (int r = 0; r < 4; r++) {
                    float l2 = sqi[mt][r >> 1] + sqj[nt][r & 1] - 2.0f * acc[mt][nt][r];
                    kkb[(mt * 16 + nt * 4 + r) * 512 + tid] = kern5b(l2, c116);
                    acc[mt][nt][r] = 0.0f;
                }
    }

    // ---- phase 2: G2 over total2 ----
    run_gemm(g_t2 + (size_t)(I * 256) * D2, g_t2 + (size_t)(J * 128) * D2,
             D2, D2 / BK, acc, sb, tid, lane, wm, wn);

    float part = 0.0f;
    {
        float c216 = g_c[1] * 0.0625f;
        float sqi[4][2], sqj[4][2];
        #pragma unroll
        for (int mt = 0; mt < 4; mt++) {
            int ib = I * 256 + wm * 64 + mt * 16 + (lane >> 2);
            sqi[mt][0] = g_sq2[ib];
            sqi[mt][1] = g_sq2[ib + 8];
        }
        #pragma unroll
        for (int nt = 0; nt < 4; nt++) {
            int jb = J * 128 + wn * 32 + nt * 8 + ((lane & 3) << 1);
            sqj[nt][0] = g_sq2[jb];
            sqj[nt][1] = g_sq2[jb + 1];
        }
        const float PC = 1.0f / (2048.0f * 2047.0f);
        const float QC = 1.0f / (2048.0f * 2048.0f);
        const float* kkb = g_kk + (size_t)blockIdx.x * 32768;
        #pragma unroll
        for (int mt = 0; mt < 4; mt++)
            #pragma unroll
            for (int nt = 0; nt < 4; nt++)
                #pragma unroll
                for (int r = 0; r < 4; r++) {
                    int i = I * 256 + wm * 64 + mt * 16 + (lane >> 2) + ((r >> 1) << 3);
                    int j = J * 128 + wn * 32 + nt * 8 + ((lane & 3) << 1) + (r & 1);
                    float l2 = sqi[mt][r >> 1] + sqj[nt][r & 1] - 2.0f * acc[mt][nt][r];
                    float k2v = kern5b(l2, c216);
                    // strictly-upper mask, x2 symmetry, +/- index-matrix coefficient
                    float coef = (i < j) ? 2.0f * (((i >> 11) == (j >> 11)) ? PC : -QC)
                                         : 0.0f;
                    part += kkb[(mt * 16 + nt * 4 + r) * 512 + tid] * k2v * coef;
                }
    }

    // deterministic CTA reduction
    #pragma unroll
    for (int o = 16; o; o >>= 1) part += __shfl_xor_sync(0xffffffffu, part, o);
    float* red = (float*)(smem + SM_RED);
    __syncthreads();
    if (lane == 0) red[wid] = part;
    __syncthreads();
    __shared__ int s_last;
    if (tid == 0) {
        float s = 0.0f;
        #pragma unroll
        for (int w = 0; w < 16; w++) s += red[w];
        g_partials[blockIdx.x] = s;
        __threadfence();
        int old = atomicAdd(&g_ctr, 1);
        s_last = (old == NTILES - 1) ? 1 : 0;
    }
    __syncthreads();

    // last CTA: deterministic final reduction (fixed-order tree), reset counter
    if (s_last) {
        __threadfence();
        double* shd = (double*)(smem + SM_RED);
        double a = 0.0;
        if (tid < 256) {
            a = (double)g_partials[tid];
            if (tid + 256 < NTILES) a += (double)g_partials[tid + 256];
            shd[tid] = a;
        }
        __syncthreads();
        for (int s = 128; s; s >>= 1) {
            if (tid < s) shd[tid] += shd[tid + s];
            __syncthreads();
        }
        if (tid == 0) {
            out[0] = (float)(shd[0] + 2.0 / 2047.0);
            g_ctr = 0;                       // reset for next graph replay
        }
    }
}

// ---------------- launch ----------------
extern "C" void kernel_launch(void* const* d_in, const int* in_sizes, int n_in,
                              void* d_out, int out_size) {
    const float* z1s = (const float*)d_in[0];
    const float* z1t = (const float*)d_in[1];
    const float* z2s = (const float*)d_in[2];
    const float* z2t = (const float*)d_in[3];

    cudaFuncSetAttribute(kmain, cudaFuncAttributeMaxDynamicSharedMemorySize, SMEM_TOTAL);

    kprep<<<512, 256>>>(z1s, z1t, z2s, z2t);
    kcol2<<<24, 256>>>();
    kconst<<<1, 256>>>();
    kmain<<<NTILES, 512, SMEM_TOTAL>>>((float*)d_out);
}

// round 14
// speedup vs baseline: 1.2332x; 1.1631x over previous
#include <cuda_runtime.h>
#include <cuda_bf16.h>
#include <cstdint>

// Problem constants
#define N_TOT 4096
#define D1    4096
#define D2    2048
#define NTI   16            // 256-row blocks
#define NTJ   32            // 128-col blocks
#define NTILES 272          // tiles (I,J) with J >= 2I
#define BK    64            // k-tile

// SMEM: 4 stages A (4x32KB) | 4 stages B (4x16KB) | reduction scratch
#define SM_ASTAGE 32768
#define SM_BSTAGE 16384
#define SM_B_OFF  131072
#define SM_RED    196608
#define SMEM_TOTAL (196608 + 128)

// ---------------- device scratch ----------------
__device__ __nv_bfloat16 g_t1[(size_t)N_TOT * D1];   // 32 MB
__device__ __nv_bfloat16 g_t2[(size_t)N_TOT * D2];   // 16 MB
__device__ float g_sq1[N_TOT];
__device__ float g_sq2[N_TOT];
__device__ float g_pcs1[(size_t)512 * D1];           // 8 MB
__device__ float g_pcs2[(size_t)512 * D2];           // 4 MB
__device__ float g_colsum1[D1];
__device__ float g_colsum2[D2];
__device__ float g_c[2];
__device__ float g_partials[NTILES];
__device__ float g_kk[(size_t)NTILES * 32768];       // 35.7 MB k1 scratch

// ---------------- helpers ----------------
__device__ __forceinline__ float ex2f(float x) {
    float y; asm("ex2.approx.ftz.f32 %0, %1;" : "=f"(y) : "f"(x)); return y;
}
// sum_{i=0..4} exp(-t/2^i) = y + y^2 + y^4 + y^8 + y^16, y = exp(-t/16)
__device__ __forceinline__ float kern5b(float l2, float c16) {
    float y = ex2f(-fmaxf(l2, 0.0f) * c16);
    float y2 = y * y, y4 = y2 * y2, y8 = y4 * y4, y16 = y8 * y8;
    return y + y2 + y4 + y8 + y16;
}
__device__ __forceinline__ void cpa16(uint32_t s, const void* g) {
    asm volatile("cp.async.cg.shared.global [%0], [%1], 16;" :: "r"(s), "l"(g));
}
__device__ __forceinline__ void ldsm4(uint32_t* r, uint32_t addr) {
    asm volatile("ldmatrix.sync.aligned.m8n8.x4.shared.b16 {%0,%1,%2,%3}, [%4];"
        : "=r"(r[0]), "=r"(r[1]), "=r"(r[2]), "=r"(r[3]) : "r"(addr));
}
__device__ __forceinline__ void mma16816(float* d, const uint32_t* a, const uint32_t* b) {
    asm volatile(
        "mma.sync.aligned.m16n8k16.row.col.f32.bf16.bf16.f32 "
        "{%0,%1,%2,%3}, {%4,%5,%6,%7}, {%8,%9}, {%0,%1,%2,%3};"
        : "+f"(d[0]), "+f"(d[1]), "+f"(d[2]), "+f"(d[3])
        : "r"(a[0]), "r"(a[1]), "r"(a[2]), "r"(a[3]), "r"(b[0]), "r"(b[1]));
}

// ---------------- pre-pass 1: convert + row sq-norms + col partial sums ----------------
__global__ void kprep(const float* __restrict__ z1s, const float* __restrict__ z1t,
                      const float* __restrict__ z2s, const float* __restrict__ z2t) {
    int bid = blockIdx.x, tid = threadIdx.x;
    int lane = tid & 31, wid = tid >> 5;
    __shared__ float sred1[8][8];
    __shared__ float sred2[8][8];
    float4 ca1[4], ca2[2];
    #pragma unroll
    for (int s = 0; s < 4; s++) ca1[s] = make_float4(0.f, 0.f, 0.f, 0.f);
    #pragma unroll
    for (int s = 0; s < 2; s++) ca2[s] = make_float4(0.f, 0.f, 0.f, 0.f);

    for (int r8 = 0; r8 < 8; r8++) {
        int r = bid * 8 + r8;
        const float4* s1 = (const float4*)((r < 2048) ? z1s + (size_t)r * D1
                                                      : z1t + (size_t)(r - 2048) * D1);
        float sq = 0.0f;
        #pragma unroll
        for (int s = 0; s < 4; s++) {
            float4 v = s1[tid + 256 * s];
            __nv_bfloat162 h0 = {__float2bfloat16(v.x), __float2bfloat16(v.y)};
            __nv_bfloat162 h1 = {__float2bfloat16(v.z), __float2bfloat16(v.w)};
            uint2 pk = {*(uint32_t*)&h0, *(uint32_t*)&h1};
            *(uint2*)(g_t1 + (size_t)r * D1 + 4 * (tid + 256 * s)) = pk;
            sq += v.x * v.x + v.y * v.y + v.z * v.z + v.w * v.w;
            ca1[s].x += v.x; ca1[s].y += v.y; ca1[s].z += v.z; ca1[s].w += v.w;
        }
        #pragma unroll
        for (int o = 16; o; o >>= 1) sq += __shfl_xor_sync(0xffffffffu, sq, o);
        if (lane == 0) sred1[r8][wid] = sq;

        const float4* s2 = (const float4*)((r < 2048) ? z2s + (size_t)r * D2
                                                      : z2t + (size_t)(r - 2048) * D2);
        sq = 0.0f;
        #pragma unroll
        for (int s = 0; s < 2; s++) {
            float4 v = s2[tid + 256 * s];
            __nv_bfloat162 h0 = {__float2bfloat16(v.x), __float2bfloat16(v.y)};
            __nv_bfloat162 h1 = {__float2bfloat16(v.z), __float2bfloat16(v.w)};
            uint2 pk = {*(uint32_t*)&h0, *(uint32_t*)&h1};
            *(uint2*)(g_t2 + (size_t)r * D2 + 4 * (tid + 256 * s)) = pk;
            sq += v.x * v.x + v.y * v.y + v.z * v.z + v.w * v.w;
            ca2[s].x += v.x; ca2[s].y += v.y; ca2[s].z += v.z; ca2[s].w += v.w;
        }
        #pragma unroll
        for (int o = 16; o; o >>= 1) sq += __shfl_xor_sync(0xffffffffu, sq, o);
        if (lane == 0) sred2[r8][wid] = sq;
    }
    #pragma unroll
    for (int s = 0; s < 4; s++)
        *(float4*)&g_pcs1[(size_t)bid * D1 + 1024 * s + 4 * tid] = ca1[s];
    #pragma unroll
    for (int s = 0; s < 2; s++)
        *(float4*)&g_pcs2[(size_t)bid * D2 + 1024 * s + 4 * tid] = ca2[s];
    __syncthreads();
    if (tid < 8) {
        float s = 0.0f;
        #pragma unroll
        for (int w = 0; w < 8; w++) s += sred1[tid][w];
        g_sq1[bid * 8 + tid] = s;
    } else if (tid < 16) {
        float s = 0.0f;
        #pragma unroll
        for (int w = 0; w < 8; w++) s += sred2[tid - 8][w];
        g_sq2[bid * 8 + tid - 8] = s;
    }
}

// ---------------- pre-pass 2: reduce col partial sums ----------------
__global__ void kcol2() {
    int tid = threadIdx.x;
    if (blockIdx.x < 16) {
        int j = blockIdx.x * 256 + tid;
        float s = 0.0f;
        for (int k = 0; k < 512; k++) s += g_pcs1[(size_t)k * D1 + j];
        g_colsum1[j] = s;
    } else {
        int j = (blockIdx.x - 16) * 256 + tid;
        float s = 0.0f;
        for (int k = 0; k < 512; k++) s += g_pcs2[(size_t)k * D2 + j];
        g_colsum2[j] = s;
    }
}

// ---------------- pre-pass 3: bandwidth constants ----------------
__global__ void kconst() {
    int tid = threadIdx.x;
    __shared__ double sh[512];

    double ssq = 0.0, ss = 0.0;
    for (int j = tid; j < D1; j += 256) { double v = (double)g_colsum1[j]; ss += v * v; }
    for (int j = tid; j < N_TOT; j += 256) ssq += (double)g_sq1[j];
    sh[tid] = ssq; sh[256 + tid] = ss; __syncthreads();
    for (int s = 128; s; s >>= 1) {
        if (tid < s) { sh[tid] += sh[tid + s]; sh[256 + tid] += sh[256 + tid + s]; }
        __syncthreads();
    }
    if (tid == 0) {
        double n = (double)N_TOT;
        double suml2 = 2.0 * n * sh[0] - 2.0 * sh[256];
        double bw = suml2 / (n * n - n) / 4.0;
        g_c[0] = (float)(1.4426950408889634 / bw);
    }
    __syncthreads();

    ssq = 0.0; ss = 0.0;
    for (int j = tid; j < D2; j += 256) { double v = (double)g_colsum2[j]; ss += v * v; }
    for (int j = tid; j < N_TOT; j += 256) ssq += (double)g_sq2[j];
    sh[tid] = ssq; sh[256 + tid] = ss; __syncthreads();
    for (int s = 128; s; s >>= 1) {
        if (tid < s) { sh[tid] += sh[tid + s]; sh[256 + tid] += sh[256 + tid + s]; }
        __syncthreads();
    }
    if (tid == 0) {
        double n = (double)N_TOT;
        double suml2 = 2.0 * n * sh[0] - 2.0 * sh[256];
        double bw = suml2 / (n * n - n) / 4.0;
        g_c[1] = (float)(1.4426950408889634 / bw);
    }
}

// ---------------- main fused kernel: 256x128 CTA, 16 warps, 64x32 warp tiles ----------------
__device__ __forceinline__ void load_tiles(uint32_t sb, int stage,
        const __nv_bfloat16* A, const __nv_bfloat16* B, int ld, int k0, int tid) {
    uint32_t sA = sb + (uint32_t)stage * SM_ASTAGE;
    uint32_t sB = sb + SM_B_OFF + (uint32_t)stage * SM_BSTAGE;
    #pragma unroll
    for (int v = 0; v < 4; v++) {               // A: 256x64 = 2048 x 16B
        int chunk = tid + v * 512;
        int row = chunk >> 3, c = chunk & 7;
        uint32_t off = (uint32_t)(row * 128 + ((c ^ (row & 7)) << 4));   // SW128
        cpa16(sA + off, A + (size_t)row * ld + k0 + c * 8);
    }
    #pragma unroll
    for (int v = 0; v < 2; v++) {               // B: 128x64 = 1024 x 16B
        int chunk = tid + v * 512;
        int row = chunk >> 3, c = chunk & 7;
        uint32_t off = (uint32_t)(row * 128 + ((c ^ (row & 7)) << 4));
        cpa16(sB + off, B + (size_t)row * ld + k0 + c * 8);
    }
}

__device__ __forceinline__ void compute_stage(uint32_t sA, uint32_t sB,
        float acc[4][4][4], int lane, int wm, int wn) {
    #pragma unroll
    for (int s16 = 0; s16 < 4; s16++) {
        uint32_t a[4][4], b[2][4];
        #pragma unroll
        for (int mt = 0; mt < 4; mt++) {
            int row = wm * 64 + mt * 16 + (lane & 15);
            int ch  = 2 * s16 + (lane >> 4);
            ldsm4(a[mt], sA + (uint32_t)(row * 128 + ((ch ^ (row & 7)) << 4)));
        }
        #pragma unroll
        for (int p = 0; p < 2; p++) {
            int g = lane >> 3;
            int row = wn * 32 + p * 16 + ((g >> 1) << 3) + (lane & 7);
            int ch  = 2 * s16 + (g & 1);
            ldsm4(b[p], sB + (uint32_t)(row * 128 + ((ch ^ (row & 7)) << 4)));
        }
        #pragma unroll
        for (int mt = 0; mt < 4; mt++)
            #pragma unroll
            for (int nt = 0; nt < 4; nt++)
                mma16816(acc[mt][nt], a[mt], &b[nt >> 1][(nt & 1) * 2]);
    }
}

__device__ void run_gemm(const __nv_bfloat16* A, const __nv_bfloat16* B, int ld,
        int nsteps, float acc[4][4][4], uint32_t sb, int tid, int lane, int wm, int wn) {
    asm volatile("cp.async.wait_group 0;");     // prior phase fully drained
    __syncthreads();
    #pragma unroll
    for (int s = 0; s < 3; s++) {
        load_tiles(sb, s, A, B, ld, s * BK, tid);
        asm volatile("cp.async.commit_group;");
    }
    for (int s = 0; s < nsteps; s++) {
        asm volatile("cp.async.wait_group 2;");
        __syncthreads();
        if (s + 3 < nsteps)
            load_tiles(sb, (s + 3) & 3, A, B, ld, (s + 3) * BK, tid);
        asm volatile("cp.async.commit_group;");
        compute_stage(sb + (uint32_t)(s & 3) * SM_ASTAGE,
                      sb + SM_B_OFF + (uint32_t)(s & 3) * SM_BSTAGE,
                      acc, lane, wm, wn);
    }
}

__global__ __launch_bounds__(512, 1) void kmain() {
    extern __shared__ __align__(16) char smem[];
    uint32_t sb = (uint32_t)__cvta_generic_to_shared(smem);
    int tid = threadIdx.x, lane = tid & 31, wid = tid >> 5;
    int wm = wid >> 2, wn = wid & 3;    // 4 x 4 warp grid, warp tile 64x32

    // tile mapping: (I,J), I in [0,16), J in [2I, 32)
    int rem = blockIdx.x, I = 0;
    while (rem >= NTJ - 2 * I) { rem -= NTJ - 2 * I; I++; }
    int J = 2 * I + rem;

    float acc[4][4][4];
    #pragma unroll
    for (int mt = 0; mt < 4; mt++)
        #pragma unroll
        for (int nt = 0; nt < 4; nt++)
            #pragma unroll
            for (int r = 0; r < 4; r++) acc[mt][nt][r] = 0.0f;

    // ---- phase 1: G1 over total1 ----
    run_gemm(g_t1 + (size_t)(I * 256) * D1, g_t1 + (size_t)(J * 128) * D1,
             D1, D1 / BK, acc, sb, tid, lane, wm, wn);

    {
        float c116 = g_c[0] * 0.0625f;
        float sqi[4][2], sqj[4][2];
        #pragma unroll
        for (int mt = 0; mt < 4; mt++) {
            int ib = I * 256 + wm * 64 + mt * 16 + (lane >> 2);
            sqi[mt][0] = g_sq1[ib];
            sqi[mt][1] = g_sq1[ib + 8];
        }
        #pragma unroll
        for (int nt = 0; nt < 4; nt++) {
            int jb = J * 128 + wn * 32 + nt * 8 + ((lane & 3) << 1);
            sqj[nt][0] = g_sq1[jb];
            sqj[nt][1] = g_sq1[jb + 1];
        }
        float* kkb = g_kk + (size_t)blockIdx.x * 32768;
        #pragma unroll
        for (int mt = 0; mt < 4; mt++)
            #pragma unroll
            for (int nt = 0; nt < 4; nt++)
                #pragma unroll
                for (int r = 0; r < 4; r++) {
                    float l2 = sqi[mt][r >> 1] + sqj[nt][r & 1] - 2.0f * acc[mt][nt][r];
                    __stcs(&kkb[(mt * 16 + nt * 4 + r) * 512 + tid], kern5b(l2, c116));
                    acc[mt][nt][r] = 0.0f;
                }
    }

    // ---- phase 2: G2 over total2 ----
    run_gemm(g_t2 + (size_t)(I * 256) * D2, g_t2 + (size_t)(J * 128) * D2,
             D2, D2 / BK, acc, sb, tid, lane, wm, wn);

    float part = 0.0f;
    {
        float c216 = g_c[1] * 0.0625f;
        float sqi[4][2], sqj[4][2];
        #pragma unroll
        for (int mt = 0; mt < 4; mt++) {
            int ib = I * 256 + wm * 64 + mt * 16 + (lane >> 2);
            sqi[mt][0] = g_sq2[ib];
            sqi[mt][1] = g_sq2[ib + 8];
        }
        #pragma unroll
        for (int nt = 0; nt < 4; nt++) {
            int jb = J * 128 + wn * 32 + nt * 8 + ((lane & 3) << 1);
            sqj[nt][0] = g_sq2[jb];
            sqj[nt][1] = g_sq2[jb + 1];
        }
        const float PC = 1.0f / (2048.0f * 2047.0f);
        const float QC = 1.0f / (2048.0f * 2048.0f);
        const float* kkb = g_kk + (size_t)blockIdx.x * 32768;
        #pragma unroll
        for (int mt = 0; mt < 4; mt++)
            #pragma unroll
            for (int nt = 0; nt < 4; nt++)
                #pragma unroll
                for (int r = 0; r < 4; r++) {
                    int i = I * 256 + wm * 64 + mt * 16 + (lane >> 2) + ((r >> 1) << 3);
                    int j = J * 128 + wn * 32 + nt * 8 + ((lane & 3) << 1) + (r & 1);
                    float l2 = sqi[mt][r >> 1] + sqj[nt][r & 1] - 2.0f * acc[mt][nt][r];
                    float k2v = kern5b(l2, c216);
                    // strictly-upper mask, x2 symmetry, +/- index-matrix coefficient
                    float coef = (i < j) ? 2.0f * (((i >> 11) == (j >> 11)) ? PC : -QC)
                                         : 0.0f;
                    part += __ldcs(&kkb[(mt * 16 + nt * 4 + r) * 512 + tid]) * k2v * coef;
                }
    }

    // deterministic CTA reduction
    #pragma unroll
    for (int o = 16; o; o >>= 1) part += __shfl_xor_sync(0xffffffffu, part, o);
    float* red = (float*)(smem + SM_RED);
    __syncthreads();
    if (lane == 0) red[wid] = part;
    __syncthreads();
    if (tid == 0) {
        float s = 0.0f;
        #pragma unroll
        for (int w = 0; w < 16; w++) s += red[w];
        g_partials[blockIdx.x] = s;
    }
}

// ---------------- final deterministic reduction ----------------
__global__ void kred(float* out) {
    int tid = threadIdx.x;
    __shared__ double sh[256];
    double a = 0.0;
    for (int i = tid; i < NTILES; i += 256) a += (double)g_partials[i];
    sh[tid] = a; __syncthreads();
    for (int s = 128; s; s >>= 1) { if (tid < s) sh[tid] += sh[tid + s]; __syncthreads(); }
    if (tid == 0) out[0] = (float)(sh[0] + 2.0 / 2047.0);
}

// ---------------- launch ----------------
extern "C" void kernel_launch(void* const* d_in, const int* in_sizes, int n_in,
                              void* d_out, int out_size) {
    const float* z1s = (const float*)d_in[0];
    const float* z1t = (const float*)d_in[1];
    const float* z2s = (const float*)d_in[2];
    const float* z2t = (const float*)d_in[3];

    cudaFuncSetAttribute(kmain, cudaFuncAttributeMaxDynamicSharedMemorySize, SMEM_TOTAL);

    kprep<<<512, 256>>>(z1s, z1t, z2s, z2t);
    kcol2<<<24, 256>>>();
    kconst<<<1, 256>>>();
    kmain<<<NTILES, 512, SMEM_TOTAL>>>();
    kred<<<1, 256>>>((float*)d_out);
}

// round 15
// speedup vs baseline: 1.2743x; 1.0333x over previous
#include <cuda_runtime.h>
#include <cuda_bf16.h>
#include <cstdint>

// Problem constants
#define N_TOT 4096
#define D1    4096
#define D2    2048
#define NTI   16            // 256-row blocks
#define NTJ   32            // 128-col blocks
#define NTILES 272          // tiles (I,J) with J >= 2I
#define BK    128           // k-tile (two SW128 half-rows per row)

// SMEM: 2 stages A (2x64KB) | 2 stages B (2x32KB) | reduction scratch
#define SM_ASTAGE 65536
#define SM_BSTAGE 32768
#define SM_B_OFF  131072
#define SM_RED    196608
#define SMEM_TOTAL (196608 + 128)

// ---------------- device scratch ----------------
__device__ __nv_bfloat16 g_t1[(size_t)N_TOT * D1];   // 32 MB
__device__ __nv_bfloat16 g_t2[(size_t)N_TOT * D2];   // 16 MB
__device__ float g_sq1[N_TOT];
__device__ float g_sq2[N_TOT];
__device__ float g_pcs1[(size_t)512 * D1];           // 8 MB
__device__ float g_pcs2[(size_t)512 * D2];           // 4 MB
__device__ float g_colsum1[D1];
__device__ float g_colsum2[D2];
__device__ float g_c[2];
__device__ float g_partials[NTILES];
__device__ float g_kk[(size_t)NTILES * 32768];       // 35.7 MB k1 scratch

// ---------------- helpers ----------------
__device__ __forceinline__ float ex2f(float x) {
    float y; asm("ex2.approx.ftz.f32 %0, %1;" : "=f"(y) : "f"(x)); return y;
}
// sum_{i=0..4} exp(-t/2^i) = y + y^2 + y^4 + y^8 + y^16, y = exp(-t/16)
__device__ __forceinline__ float kern5b(float l2, float c16) {
    float y = ex2f(-fmaxf(l2, 0.0f) * c16);
    float y2 = y * y, y4 = y2 * y2, y8 = y4 * y4, y16 = y8 * y8;
    return y + y2 + y4 + y8 + y16;
}
__device__ __forceinline__ void cpa16(uint32_t s, const void* g) {
    asm volatile("cp.async.cg.shared.global [%0], [%1], 16;" :: "r"(s), "l"(g));
}
__device__ __forceinline__ void ldsm4(uint32_t* r, uint32_t addr) {
    asm volatile("ldmatrix.sync.aligned.m8n8.x4.shared.b16 {%0,%1,%2,%3}, [%4];"
        : "=r"(r[0]), "=r"(r[1]), "=r"(r[2]), "=r"(r[3]) : "r"(addr));
}
__device__ __forceinline__ void mma16816(float* d, const uint32_t* a, const uint32_t* b) {
    asm volatile(
        "mma.sync.aligned.m16n8k16.row.col.f32.bf16.bf16.f32 "
        "{%0,%1,%2,%3}, {%4,%5,%6,%7}, {%8,%9}, {%0,%1,%2,%3};"
        : "+f"(d[0]), "+f"(d[1]), "+f"(d[2]), "+f"(d[3])
        : "r"(a[0]), "r"(a[1]), "r"(a[2]), "r"(a[3]), "r"(b[0]), "r"(b[1]));
}

// swizzled offset inside a tile with 256B rows (two SW128 half-rows):
// ch = 16B chunk index within the row (0..15)
__device__ __forceinline__ uint32_t sw256(int row, int ch) {
    return (uint32_t)(row * 256 + ((ch >> 3) << 7) + (((ch & 7) ^ (row & 7)) << 4));
}

// ---------------- pre-pass 1: convert + row sq-norms + col partial sums ----------------
__global__ void kprep(const float* __restrict__ z1s, const float* __restrict__ z1t,
                      const float* __restrict__ z2s, const float* __restrict__ z2t) {
    int bid = blockIdx.x, tid = threadIdx.x;
    int lane = tid & 31, wid = tid >> 5;
    __shared__ float sred1[8][8];
    __shared__ float sred2[8][8];
    float4 ca1[4], ca2[2];
    #pragma unroll
    for (int s = 0; s < 4; s++) ca1[s] = make_float4(0.f, 0.f, 0.f, 0.f);
    #pragma unroll
    for (int s = 0; s < 2; s++) ca2[s] = make_float4(0.f, 0.f, 0.f, 0.f);

    for (int r8 = 0; r8 < 8; r8++) {
        int r = bid * 8 + r8;
        const float4* s1 = (const float4*)((r < 2048) ? z1s + (size_t)r * D1
                                                      : z1t + (size_t)(r - 2048) * D1);
        float sq = 0.0f;
        #pragma unroll
        for (int s = 0; s < 4; s++) {
            float4 v = s1[tid + 256 * s];
            __nv_bfloat162 h0 = {__float2bfloat16(v.x), __float2bfloat16(v.y)};
            __nv_bfloat162 h1 = {__float2bfloat16(v.z), __float2bfloat16(v.w)};
            uint2 pk = {*(uint32_t*)&h0, *(uint32_t*)&h1};
            *(uint2*)(g_t1 + (size_t)r * D1 + 4 * (tid + 256 * s)) = pk;
            sq += v.x * v.x + v.y * v.y + v.z * v.z + v.w * v.w;
            ca1[s].x += v.x; ca1[s].y += v.y; ca1[s].z += v.z; ca1[s].w += v.w;
        }
        #pragma unroll
        for (int o = 16; o; o >>= 1) sq += __shfl_xor_sync(0xffffffffu, sq, o);
        if (lane == 0) sred1[r8][wid] = sq;

        const float4* s2 = (const float4*)((r < 2048) ? z2s + (size_t)r * D2
                                                      : z2t + (size_t)(r - 2048) * D2);
        sq = 0.0f;
        #pragma unroll
        for (int s = 0; s < 2; s++) {
            float4 v = s2[tid + 256 * s];
            __nv_bfloat162 h0 = {__float2bfloat16(v.x), __float2bfloat16(v.y)};
            __nv_bfloat162 h1 = {__float2bfloat16(v.z), __float2bfloat16(v.w)};
            uint2 pk = {*(uint32_t*)&h0, *(uint32_t*)&h1};
            *(uint2*)(g_t2 + (size_t)r * D2 + 4 * (tid + 256 * s)) = pk;
            sq += v.x * v.x + v.y * v.y + v.z * v.z + v.w * v.w;
            ca2[s].x += v.x; ca2[s].y += v.y; ca2[s].z += v.z; ca2[s].w += v.w;
        }
        #pragma unroll
        for (int o = 16; o; o >>= 1) sq += __shfl_xor_sync(0xffffffffu, sq, o);
        if (lane == 0) sred2[r8][wid] = sq;
    }
    #pragma unroll
    for (int s = 0; s < 4; s++)
        *(float4*)&g_pcs1[(size_t)bid * D1 + 1024 * s + 4 * tid] = ca1[s];
    #pragma unroll
    for (int s = 0; s < 2; s++)
        *(float4*)&g_pcs2[(size_t)bid * D2 + 1024 * s + 4 * tid] = ca2[s];
    __syncthreads();
    if (tid < 8) {
        float s = 0.0f;
        #pragma unroll
        for (int w = 0; w < 8; w++) s += sred1[tid][w];
        g_sq1[bid * 8 + tid] = s;
    } else if (tid < 16) {
        float s = 0.0f;
        #pragma unroll
        for (int w = 0; w < 8; w++) s += sred2[tid - 8][w];
        g_sq2[bid * 8 + tid - 8] = s;
    }
}

// ---------------- pre-pass 2: reduce col partial sums ----------------
__global__ void kcol2() {
    int tid = threadIdx.x;
    if (blockIdx.x < 16) {
        int j = blockIdx.x * 256 + tid;
        float s = 0.0f;
        for (int k = 0; k < 512; k++) s += g_pcs1[(size_t)k * D1 + j];
        g_colsum1[j] = s;
    } else {
        int j = (blockIdx.x - 16) * 256 + tid;
        float s = 0.0f;
        for (int k = 0; k < 512; k++) s += g_pcs2[(size_t)k * D2 + j];
        g_colsum2[j] = s;
    }
}

// ---------------- pre-pass 3: bandwidth constants ----------------
__global__ void kconst() {
    int tid = threadIdx.x;
    __shared__ double sh[512];

    double ssq = 0.0, ss = 0.0;
    for (int j = tid; j < D1; j += 256) { double v = (double)g_colsum1[j]; ss += v * v; }
    for (int j = tid; j < N_TOT; j += 256) ssq += (double)g_sq1[j];
    sh[tid] = ssq; sh[256 + tid] = ss; __syncthreads();
    for (int s = 128; s; s >>= 1) {
        if (tid < s) { sh[tid] += sh[tid + s]; sh[256 + tid] += sh[256 + tid + s]; }
        __syncthreads();
    }
    if (tid == 0) {
        double n = (double)N_TOT;
        double suml2 = 2.0 * n * sh[0] - 2.0 * sh[256];
        double bw = suml2 / (n * n - n) / 4.0;
        g_c[0] = (float)(1.4426950408889634 / bw);
    }
    __syncthreads();

    ssq = 0.0; ss = 0.0;
    for (int j = tid; j < D2; j += 256) { double v = (double)g_colsum2[j]; ss += v * v; }
    for (int j = tid; j < N_TOT; j += 256) ssq += (double)g_sq2[j];
    sh[tid] = ssq; sh[256 + tid] = ss; __syncthreads();
    for (int s = 128; s; s >>= 1) {
        if (tid < s) { sh[tid] += sh[tid + s]; sh[256 + tid] += sh[256 + tid + s]; }
        __syncthreads();
    }
    if (tid == 0) {
        double n = (double)N_TOT;
        double suml2 = 2.0 * n * sh[0] - 2.0 * sh[256];
        double bw = suml2 / (n * n - n) / 4.0;
        g_c[1] = (float)(1.4426950408889634 / bw);
    }
}

// ---------------- main fused kernel: 256x128 CTA, BK=128, 2-stage ----------------
__device__ __forceinline__ void load_tiles(uint32_t sb, int stage,
        const __nv_bfloat16* A, const __nv_bfloat16* B, int ld, int k0, int tid) {
    uint32_t sA = sb + (uint32_t)stage * SM_ASTAGE;
    uint32_t sB = sb + SM_B_OFF + (uint32_t)stage * SM_BSTAGE;
    #pragma unroll
    for (int v = 0; v < 8; v++) {               // A: 256 rows x 16 chunks = 4096 x 16B
        int chunk = tid + v * 512;
        int row = chunk >> 4, c = chunk & 15;
        cpa16(sA + sw256(row, c), A + (size_t)row * ld + k0 + c * 8);
    }
    #pragma unroll
    for (int v = 0; v < 4; v++) {               // B: 128 rows x 16 chunks = 2048 x 16B
        int chunk = tid + v * 512;
        int row = chunk >> 4, c = chunk & 15;
        cpa16(sB + sw256(row, c), B + (size_t)row * ld + k0 + c * 8);
    }
}

__device__ __forceinline__ void compute_stage(uint32_t sA, uint32_t sB,
        float acc[4][4][4], int lane, int wm, int wn) {
    #pragma unroll
    for (int s16 = 0; s16 < 8; s16++) {
        uint32_t a[4][4], b[2][4];
        #pragma unroll
        for (int mt = 0; mt < 4; mt++) {
            int row = wm * 64 + mt * 16 + (lane & 15);
            int ch  = 2 * s16 + (lane >> 4);
            ldsm4(a[mt], sA + sw256(row, ch));
        }
        #pragma unroll
        for (int p = 0; p < 2; p++) {
            int g = lane >> 3;
            int row = wn * 32 + p * 16 + ((g >> 1) << 3) + (lane & 7);
            int ch  = 2 * s16 + (g & 1);
            ldsm4(b[p], sB + sw256(row, ch));
        }
        #pragma unroll
        for (int mt = 0; mt < 4; mt++)
            #pragma unroll
            for (int nt = 0; nt < 4; nt++)
                mma16816(acc[mt][nt], a[mt], &b[nt >> 1][(nt & 1) * 2]);
    }
}

__device__ void run_gemm(const __nv_bfloat16* A, const __nv_bfloat16* B, int ld,
        int nsteps, float acc[4][4][4], uint32_t sb, int tid, int lane, int wm, int wn) {
    asm volatile("cp.async.wait_group 0;");     // prior phase fully drained
    __syncthreads();
    load_tiles(sb, 0, A, B, ld, 0, tid);
    asm volatile("cp.async.commit_group;");
    for (int s = 0; s < nsteps; s++) {
        asm volatile("cp.async.wait_group 0;"); // stage s resident
        __syncthreads();                        // also: all warps done with stage s-1
        if (s + 1 < nsteps) {
            load_tiles(sb, (s + 1) & 1, A, B, ld, (s + 1) * BK, tid);
            asm volatile("cp.async.commit_group;");
        }
        compute_stage(sb + (uint32_t)(s & 1) * SM_ASTAGE,
                      sb + SM_B_OFF + (uint32_t)(s & 1) * SM_BSTAGE,
                      acc, lane, wm, wn);
    }
}

__global__ __launch_bounds__(512, 1) void kmain() {
    extern __shared__ __align__(16) char smem[];
    uint32_t sb = (uint32_t)__cvta_generic_to_shared(smem);
    int tid = threadIdx.x, lane = tid & 31, wid = tid >> 5;
    int wm = wid >> 2, wn = wid & 3;    // 4 x 4 warp grid, warp tile 64x32

    // tile mapping: (I,J), I in [0,16), J in [2I, 32)
    int rem = blockIdx.x, I = 0;
    while (rem >= NTJ - 2 * I) { rem -= NTJ - 2 * I; I++; }
    int J = 2 * I + rem;

    float acc[4][4][4];
    #pragma unroll
    for (int mt = 0; mt < 4; mt++)
        #pragma unroll
        for (int nt = 0; nt < 4; nt++)
            #pragma unroll
            for (int r = 0; r < 4; r++) acc[mt][nt][r] = 0.0f;

    // ---- phase 1: G1 over total1 ----
    run_gemm(g_t1 + (size_t)(I * 256) * D1, g_t1 + (size_t)(J * 128) * D1,
             D1, D1 / BK, acc, sb, tid, lane, wm, wn);

    {
        float c116 = g_c[0] * 0.0625f;
        float sqi[4][2], sqj[4][2];
        #pragma unroll
        for (int mt = 0; mt < 4; mt++) {
            int ib = I * 256 + wm * 64 + mt * 16 + (lane >> 2);
            sqi[mt][0] = g_sq1[ib];
            sqi[mt][1] = g_sq1[ib + 8];
        }
        #pragma unroll
        for (int nt = 0; nt < 4; nt++) {
            int jb = J * 128 + wn * 32 + nt * 8 + ((lane & 3) << 1);
            sqj[nt][0] = g_sq1[jb];
            sqj[nt][1] = g_sq1[jb + 1];
        }
        float* kkb = g_kk + (size_t)blockIdx.x * 32768;
        #pragma unroll
        for (int mt = 0; mt < 4; mt++)
            #pragma unroll
            for (int nt = 0; nt < 4; nt++)
                #pragma unroll
                for (int r = 0; r < 4; r++) {
                    float l2 = sqi[mt][r >> 1] + sqj[nt][r & 1] - 2.0f * acc[mt][nt][r];
                    kkb[(mt * 16 + nt * 4 + r) * 512 + tid] = kern5b(l2, c116);
                    acc[mt][nt][r] = 0.0f;
                }
    }

    // ---- phase 2: G2 over total2 ----
    run_gemm(g_t2 + (size_t)(I * 256) * D2, g_t2 + (size_t)(J * 128) * D2,
             D2, D2 / BK, acc, sb, tid, lane, wm, wn);

    float part = 0.0f;
    {
        float c216 = g_c[1] * 0.0625f;
        float sqi[4][2], sqj[4][2];
        #pragma unroll
        for (int mt = 0; mt < 4; mt++) {
            int ib = I * 256 + wm * 64 + mt * 16 + (lane >> 2);
            sqi[mt][0] = g_sq2[ib];
            sqi[mt][1] = g_sq2[ib + 8];
        }
        #pragma unroll
        for (int nt = 0; nt < 4; nt++) {
            int jb = J * 128 + wn * 32 + nt * 8 + ((lane & 3) << 1);
            sqj[nt][0] = g_sq2[jb];
            sqj[nt][1] = g_sq2[jb + 1];
        }
        const float PC = 1.0f / (2048.0f * 2047.0f);
        const float QC = 1.0f / (2048.0f * 2048.0f);
        const float* kkb = g_kk + (size_t)blockIdx.x * 32768;
        #pragma unroll
        for (int mt = 0; mt < 4; mt++)
            #pragma unroll
            for (int nt = 0; nt < 4; nt++)
                #pragma unroll
                for (int r = 0; r < 4; r++) {
                    int i = I * 256 + wm * 64 + mt * 16 + (lane >> 2) + ((r >> 1) << 3);
                    int j = J * 128 + wn * 32 + nt * 8 + ((lane & 3) << 1) + (r & 1);
                    float l2 = sqi[mt][r >> 1] + sqj[nt][r & 1] - 2.0f * acc[mt][nt][r];
                    float k2v = kern5b(l2, c216);
                    // strictly-upper mask, x2 symmetry, +/- index-matrix coefficient
                    float coef = (i < j) ? 2.0f * (((i >> 11) == (j >> 11)) ? PC : -QC)
                                         : 0.0f;
                    part += kkb[(mt * 16 + nt * 4 + r) * 512 + tid] * k2v * coef;
                }
    }

    // deterministic CTA reduction
    #pragma unroll
    for (int o = 16; o; o >>= 1) part += __shfl_xor_sync(0xffffffffu, part, o);
    float* red = (float*)(smem + SM_RED);
    __syncthreads();
    if (lane == 0) red[wid] = part;
    __syncthreads();
    if (tid == 0) {
        float s = 0.0f;
        #pragma unroll
        for (int w = 0; w < 16; w++) s += red[w];
        g_partials[blockIdx.x] = s;
    }
}

// ---------------- final deterministic reduction ----------------
__global__ void kred(float* out) {
    int tid = threadIdx.x;
    __shared__ double sh[256];
    double a = 0.0;
    for (int i = tid; i < NTILES; i += 256) a += (double)g_partials[i];
    sh[tid] = a; __syncthreads();
    for (int s = 128; s; s >>= 1) { if (tid < s) sh[tid] += sh[tid + s]; __syncthreads(); }
    if (tid == 0) out[0] = (float)(sh[0] + 2.0 / 2047.0);
}

// ---------------- launch ----------------
extern "C" void kernel_launch(void* const* d_in, const int* in_sizes, int n_in,
                              void* d_out, int out_size) {
    const float* z1s = (const float*)d_in[0];
    const float* z1t = (const float*)d_in[1];
    const float* z2s = (const float*)d_in[2];
    const float* z2t = (const float*)d_in[3];

    cudaFuncSetAttribute(kmain, cudaFuncAttributeMaxDynamicSharedMemorySize, SMEM_TOTAL);

    kprep<<<512, 256>>>(z1s, z1t, z2s, z2t);
    kcol2<<<24, 256>>>();
    kconst<<<1, 256>>>();
    kmain<<<NTILES, 512, SMEM_TOTAL>>>();
    kred<<<1, 256>>>((float*)d_out);
}

// round 16
// speedup vs baseline: 1.2817x; 1.0058x over previous
#include <cuda_runtime.h>
#include <cuda_bf16.h>
#include <cstdint>

// Problem constants
#define N_TOT 4096
#define D1    4096
#define D2    2048
#define NTI   16            // 256-row blocks
#define NTJ   32            // 128-col blocks
#define NTILES 272          // tiles (I,J) with J >= 2I
#define BK    128           // k-tile (two SW128 half-rows per row)

// SMEM: 2 stages A (2x64KB) | 2 stages B (2x32KB) | reduction scratch
#define SM_ASTAGE 65536
#define SM_BSTAGE 32768
#define SM_B_OFF  131072
#define SM_RED    196608
#define SMEM_TOTAL (196608 + 128)

// ---------------- device scratch ----------------
__device__ __nv_bfloat16 g_t1[(size_t)N_TOT * D1];   // 32 MB
__device__ __nv_bfloat16 g_t2[(size_t)N_TOT * D2];   // 16 MB
__device__ float g_sq1[N_TOT];
__device__ float g_sq2[N_TOT];
__device__ float g_pcs1[(size_t)512 * D1];           // 8 MB
__device__ float g_pcs2[(size_t)512 * D2];           // 4 MB
__device__ float g_colsum1[D1];
__device__ float g_colsum2[D2];
__device__ float g_c[2];
__device__ float g_partials[NTILES];
__device__ float g_kk[(size_t)NTILES * 32768];       // 35.7 MB k1 scratch

// ---------------- helpers ----------------
__device__ __forceinline__ float ex2f(float x) {
    float y; asm("ex2.approx.ftz.f32 %0, %1;" : "=f"(y) : "f"(x)); return y;
}
// sum_{i=0..4} exp(-t/2^i) = y + y^2 + y^4 + y^8 + y^16, y = exp(-t/16)
__device__ __forceinline__ float kern5b(float l2, float c16) {
    float y = ex2f(-fmaxf(l2, 0.0f) * c16);
    float y2 = y * y, y4 = y2 * y2, y8 = y4 * y4, y16 = y8 * y8;
    return y + y2 + y4 + y8 + y16;
}
__device__ __forceinline__ void cpa16(uint32_t s, const void* g) {
    asm volatile("cp.async.cg.shared.global [%0], [%1], 16;" :: "r"(s), "l"(g));
}
__device__ __forceinline__ void ldsm4(uint32_t* r, uint32_t addr) {
    asm volatile("ldmatrix.sync.aligned.m8n8.x4.shared.b16 {%0,%1,%2,%3}, [%4];"
        : "=r"(r[0]), "=r"(r[1]), "=r"(r[2]), "=r"(r[3]) : "r"(addr));
}
__device__ __forceinline__ void mma16816(float* d, const uint32_t* a, const uint32_t* b) {
    asm volatile(
        "mma.sync.aligned.m16n8k16.row.col.f32.bf16.bf16.f32 "
        "{%0,%1,%2,%3}, {%4,%5,%6,%7}, {%8,%9}, {%0,%1,%2,%3};"
        : "+f"(d[0]), "+f"(d[1]), "+f"(d[2]), "+f"(d[3])
        : "r"(a[0]), "r"(a[1]), "r"(a[2]), "r"(a[3]), "r"(b[0]), "r"(b[1]));
}

// swizzled offset inside a tile with 256B rows (two SW128 half-rows):
// ch = 16B chunk index within the row (0..15)
__device__ __forceinline__ uint32_t sw256(int row, int ch) {
    return (uint32_t)(row * 256 + ((ch >> 3) << 7) + (((ch & 7) ^ (row & 7)) << 4));
}

// ---------------- pre-pass 1: convert + row sq-norms + col partial sums ----------------
// 512 blocks x 512 threads: 8 rows per block, ~1770 resident threads/SM
__global__ __launch_bounds__(512) void kprep(
        const float* __restrict__ z1s, const float* __restrict__ z1t,
        const float* __restrict__ z2s, const float* __restrict__ z2t) {
    int bid = blockIdx.x, tid = threadIdx.x;
    int lane = tid & 31, wid = tid >> 5;
    __shared__ float sred1[8][16];
    __shared__ float sred2[8][16];
    float4 ca1[2], ca2;
    ca1[0] = make_float4(0.f, 0.f, 0.f, 0.f);
    ca1[1] = make_float4(0.f, 0.f, 0.f, 0.f);
    ca2 = make_float4(0.f, 0.f, 0.f, 0.f);

    for (int r8 = 0; r8 < 8; r8++) {
        int r = bid * 8 + r8;
        const float4* s1 = (const float4*)((r < 2048) ? z1s + (size_t)r * D1
                                                      : z1t + (size_t)(r - 2048) * D1);
        float sq = 0.0f;
        #pragma unroll
        for (int s = 0; s < 2; s++) {
            float4 v = s1[tid + 512 * s];
            __nv_bfloat162 h0 = {__float2bfloat16(v.x), __float2bfloat16(v.y)};
            __nv_bfloat162 h1 = {__float2bfloat16(v.z), __float2bfloat16(v.w)};
            uint2 pk = {*(uint32_t*)&h0, *(uint32_t*)&h1};
            *(uint2*)(g_t1 + (size_t)r * D1 + 4 * (tid + 512 * s)) = pk;
            sq += v.x * v.x + v.y * v.y + v.z * v.z + v.w * v.w;
            ca1[s].x += v.x; ca1[s].y += v.y; ca1[s].z += v.z; ca1[s].w += v.w;
        }
        #pragma unroll
        for (int o = 16; o; o >>= 1) sq += __shfl_xor_sync(0xffffffffu, sq, o);
        if (lane == 0) sred1[r8][wid] = sq;

        const float4* s2 = (const float4*)((r < 2048) ? z2s + (size_t)r * D2
                                                      : z2t + (size_t)(r - 2048) * D2);
        {
            float4 v = s2[tid];
            __nv_bfloat162 h0 = {__float2bfloat16(v.x), __float2bfloat16(v.y)};
            __nv_bfloat162 h1 = {__float2bfloat16(v.z), __float2bfloat16(v.w)};
            uint2 pk = {*(uint32_t*)&h0, *(uint32_t*)&h1};
            *(uint2*)(g_t2 + (size_t)r * D2 + 4 * tid) = pk;
            float sq2v = v.x * v.x + v.y * v.y + v.z * v.z + v.w * v.w;
            ca2.x += v.x; ca2.y += v.y; ca2.z += v.z; ca2.w += v.w;
            #pragma unroll
            for (int o = 16; o; o >>= 1) sq2v += __shfl_xor_sync(0xffffffffu, sq2v, o);
            if (lane == 0) sred2[r8][wid] = sq2v;
        }
    }
    #pragma unroll
    for (int s = 0; s < 2; s++)
        *(float4*)&g_pcs1[(size_t)bid * D1 + 2048 * s + 4 * tid] = ca1[s];
    *(float4*)&g_pcs2[(size_t)bid * D2 + 4 * tid] = ca2;
    __syncthreads();
    if (tid < 8) {
        float s = 0.0f;
        #pragma unroll
        for (int w = 0; w < 16; w++) s += sred1[tid][w];
        g_sq1[bid * 8 + tid] = s;
    } else if (tid < 16) {
        float s = 0.0f;
        #pragma unroll
        for (int w = 0; w < 16; w++) s += sred2[tid - 8][w];
        g_sq2[bid * 8 + tid - 8] = s;
    }
}

// ---------------- pre-pass 2: reduce col partial sums ----------------
__global__ void kcol2() {
    int tid = threadIdx.x;
    if (blockIdx.x < 16) {
        int j = blockIdx.x * 256 + tid;
        float s = 0.0f;
        for (int k = 0; k < 512; k++) s += g_pcs1[(size_t)k * D1 + j];
        g_colsum1[j] = s;
    } else {
        int j = (blockIdx.x - 16) * 256 + tid;
        float s = 0.0f;
        for (int k = 0; k < 512; k++) s += g_pcs2[(size_t)k * D2 + j];
        g_colsum2[j] = s;
    }
}

// ---------------- pre-pass 3: bandwidth constants ----------------
__global__ void kconst() {
    int tid = threadIdx.x;
    __shared__ double sh[512];

    double ssq = 0.0, ss = 0.0;
    for (int j = tid; j < D1; j += 256) { double v = (double)g_colsum1[j]; ss += v * v; }
    for (int j = tid; j < N_TOT; j += 256) ssq += (double)g_sq1[j];
    sh[tid] = ssq; sh[256 + tid] = ss; __syncthreads();
    for (int s = 128; s; s >>= 1) {
        if (tid < s) { sh[tid] += sh[tid + s]; sh[256 + tid] += sh[256 + tid + s]; }
        __syncthreads();
    }
    if (tid == 0) {
        double n = (double)N_TOT;
        double suml2 = 2.0 * n * sh[0] - 2.0 * sh[256];
        double bw = suml2 / (n * n - n) / 4.0;
        g_c[0] = (float)(1.4426950408889634 / bw);
    }
    __syncthreads();

    ssq = 0.0; ss = 0.0;
    for (int j = tid; j < D2; j += 256) { double v = (double)g_colsum2[j]; ss += v * v; }
    for (int j = tid; j < N_TOT; j += 256) ssq += (double)g_sq2[j];
    sh[tid] = ssq; sh[256 + tid] = ss; __syncthreads();
    for (int s = 128; s; s >>= 1) {
        if (tid < s) { sh[tid] += sh[tid + s]; sh[256 + tid] += sh[256 + tid + s]; }
        __syncthreads();
    }
    if (tid == 0) {
        double n = (double)N_TOT;
        double suml2 = 2.0 * n * sh[0] - 2.0 * sh[256];
        double bw = suml2 / (n * n - n) / 4.0;
        g_c[1] = (float)(1.4426950408889634 / bw);
    }
}

// ---------------- main fused kernel: 256x128 CTA, BK=128, 2-stage ----------------
__device__ __forceinline__ void load_tiles(uint32_t sb, int stage,
        const __nv_bfloat16* A, const __nv_bfloat16* B, int ld, int k0, int tid) {
    uint32_t sA = sb + (uint32_t)stage * SM_ASTAGE;
    uint32_t sB = sb + SM_B_OFF + (uint32_t)stage * SM_BSTAGE;
    #pragma unroll
    for (int v = 0; v < 8; v++) {               // A: 256 rows x 16 chunks = 4096 x 16B
        int chunk = tid + v * 512;
        int row = chunk >> 4, c = chunk & 15;
        cpa16(sA + sw256(row, c), A + (size_t)row * ld + k0 + c * 8);
    }
    #pragma unroll
    for (int v = 0; v < 4; v++) {               // B: 128 rows x 16 chunks = 2048 x 16B
        int chunk = tid + v * 512;
        int row = chunk >> 4, c = chunk & 15;
        cpa16(sB + sw256(row, c), B + (size_t)row * ld + k0 + c * 8);
    }
}

__device__ __forceinline__ void compute_stage(uint32_t sA, uint32_t sB,
        float acc[4][4][4], int lane, int wm, int wn) {
    #pragma unroll
    for (int s16 = 0; s16 < 8; s16++) {
        uint32_t a[4][4], b[2][4];
        #pragma unroll
        for (int mt = 0; mt < 4; mt++) {
            int row = wm * 64 + mt * 16 + (lane & 15);
            int ch  = 2 * s16 + (lane >> 4);
            ldsm4(a[mt], sA + sw256(row, ch));
        }
        #pragma unroll
        for (int p = 0; p < 2; p++) {
            int g = lane >> 3;
            int row = wn * 32 + p * 16 + ((g >> 1) << 3) + (lane & 7);
            int ch  = 2 * s16 + (g & 1);
            ldsm4(b[p], sB + sw256(row, ch));
        }
        #pragma unroll
        for (int mt = 0; mt < 4; mt++)
            #pragma unroll
            for (int nt = 0; nt < 4; nt++)
                mma16816(acc[mt][nt], a[mt], &b[nt >> 1][(nt & 1) * 2]);
    }
}

__device__ void run_gemm(const __nv_bfloat16* A, const __nv_bfloat16* B, int ld,
        int nsteps, float acc[4][4][4], uint32_t sb, int tid, int lane, int wm, int wn) {
    asm volatile("cp.async.wait_group 0;");     // prior phase fully drained
    __syncthreads();
    load_tiles(sb, 0, A, B, ld, 0, tid);
    asm volatile("cp.async.commit_group;");
    for (int s = 0; s < nsteps; s++) {
        asm volatile("cp.async.wait_group 0;"); // stage s resident
        __syncthreads();                        // also: all warps done with stage s-1
        if (s + 1 < nsteps) {
            load_tiles(sb, (s + 1) & 1, A, B, ld, (s + 1) * BK, tid);
            asm volatile("cp.async.commit_group;");
        }
        compute_stage(sb + (uint32_t)(s & 1) * SM_ASTAGE,
                      sb + SM_B_OFF + (uint32_t)(s & 1) * SM_BSTAGE,
                      acc, lane, wm, wn);
    }
}

__global__ __launch_bounds__(512, 1) void kmain() {
    extern __shared__ __align__(16) char smem[];
    uint32_t sb = (uint32_t)__cvta_generic_to_shared(smem);
    int tid = threadIdx.x, lane = tid & 31, wid = tid >> 5;
    int wm = wid >> 2, wn = wid & 3;    // 4 x 4 warp grid, warp tile 64x32

    // tile mapping: (I,J), I in [0,16), J in [2I, 32)
    int rem = blockIdx.x, I = 0;
    while (rem >= NTJ - 2 * I) { rem -= NTJ - 2 * I; I++; }
    int J = 2 * I + rem;

    float acc[4][4][4];
    #pragma unroll
    for (int mt = 0; mt < 4; mt++)
        #pragma unroll
        for (int nt = 0; nt < 4; nt++)
            #pragma unroll
            for (int r = 0; r < 4; r++) acc[mt][nt][r] = 0.0f;

    // ---- phase 1: G1 over total1 ----
    run_gemm(g_t1 + (size_t)(I * 256) * D1, g_t1 + (size_t)(J * 128) * D1,
             D1, D1 / BK, acc, sb, tid, lane, wm, wn);

    {
        float c116 = g_c[0] * 0.0625f;
        float sqi[4][2], sqj[4][2];
        #pragma unroll
        for (int mt = 0; mt < 4; mt++) {
            int ib = I * 256 + wm * 64 + mt * 16 + (lane >> 2);
            sqi[mt][0] = g_sq1[ib];
            sqi[mt][1] = g_sq1[ib + 8];
        }
        #pragma unroll
        for (int nt = 0; nt < 4; nt++) {
            int jb = J * 128 + wn * 32 + nt * 8 + ((lane & 3) << 1);
            sqj[nt][0] = g_sq1[jb];
            sqj[nt][1] = g_sq1[jb + 1];
        }
        float* kkb = g_kk + (size_t)blockIdx.x * 32768;
        #pragma unroll
        for (int mt = 0; mt < 4; mt++)
            #pragma unroll
            for (int nt = 0; nt < 4; nt++)
                #pragma unroll
                for (int r = 0; r < 4; r++) {
                    float l2 = sqi[mt][r >> 1] + sqj[nt][r & 1] - 2.0f * acc[mt][nt][r];
                    kkb[(mt * 16 + nt * 4 + r) * 512 + tid] = kern5b(l2, c116);
                    acc[mt][nt][r] = 0.0f;
                }
    }

    // ---- phase 2: G2 over total2 ----
    run_gemm(g_t2 + (size_t)(I * 256) * D2, g_t2 + (size_t)(J * 128) * D2,
             D2, D2 / BK, acc, sb, tid, lane, wm, wn);

    float part = 0.0f;
    {
        float c216 = g_c[1] * 0.0625f;
        float sqi[4][2], sqj[4][2];
        #pragma unroll
        for (int mt = 0; mt < 4; mt++) {
            int ib = I * 256 + wm * 64 + mt * 16 + (lane >> 2);
            sqi[mt][0] = g_sq2[ib];
            sqi[mt][1] = g_sq2[ib + 8];
        }
        #pragma unroll
        for (int nt = 0; nt < 4; nt++) {
            int jb = J * 128 + wn * 32 + nt * 8 + ((lane & 3) << 1);
            sqj[nt][0] = g_sq2[jb];
            sqj[nt][1] = g_sq2[jb + 1];
        }
        const float PC = 1.0f / (2048.0f * 2047.0f);
        const float QC = 1.0f / (2048.0f * 2048.0f);
        const float* kkb = g_kk + (size_t)blockIdx.x * 32768;
        #pragma unroll
        for (int mt = 0; mt < 4; mt++)
            #pragma unroll
            for (int nt = 0; nt < 4; nt++)
                #pragma unroll
                for (int r = 0; r < 4; r++) {
                    int i = I * 256 + wm * 64 + mt * 16 + (lane >> 2) + ((r >> 1) << 3);
                    int j = J * 128 + wn * 32 + nt * 8 + ((lane & 3) << 1) + (r & 1);
                    float l2 = sqi[mt][r >> 1] + sqj[nt][r & 1] - 2.0f * acc[mt][nt][r];
                    float k2v = kern5b(l2, c216);
                    // strictly-upper mask, x2 symmetry, +/- index-matrix coefficient
                    float coef = (i < j) ? 2.0f * (((i >> 11) == (j >> 11)) ? PC : -QC)
                                         : 0.0f;
                    part += kkb[(mt * 16 + nt * 4 + r) * 512 + tid] * k2v * coef;
                }
    }

    // deterministic CTA reduction
    #pragma unroll
    for (int o = 16; o; o >>= 1) part += __shfl_xor_sync(0xffffffffu, part, o);
    float* red = (float*)(smem + SM_RED);
    __syncthreads();
    if (lane == 0) red[wid] = part;
    __syncthreads();
    if (tid == 0) {
        float s = 0.0f;
        #pragma unroll
        for (int w = 0; w < 16; w++) s += red[w];
        g_partials[blockIdx.x] = s;
    }
}

// ---------------- final deterministic reduction ----------------
__global__ void kred(float* out) {
    int tid = threadIdx.x;
    __shared__ double sh[256];
    double a = 0.0;
    for (int i = tid; i < NTILES; i += 256) a += (double)g_partials[i];
    sh[tid] = a; __syncthreads();
    for (int s = 128; s; s >>= 1) { if (tid < s) sh[tid] += sh[tid + s]; __syncthreads(); }
    if (tid == 0) out[0] = (float)(sh[0] + 2.0 / 2047.0);
}

// ---------------- launch ----------------
extern "C" void kernel_launch(void* const* d_in, const int* in_sizes, int n_in,
                              void* d_out, int out_size) {
    const float* z1s = (const float*)d_in[0];
    const float* z1t = (const float*)d_in[1];
    const float* z2s = (const float*)d_in[2];
    const float* z2t = (const float*)d_in[3];

    cudaFuncSetAttribute(kmain, cudaFuncAttributeMaxDynamicSharedMemorySize, SMEM_TOTAL);

    kprep<<<512, 512>>>(z1s, z1t, z2s, z2t);
    kcol2<<<24, 256>>>();
    kconst<<<1, 256>>>();
    kmain<<<NTILES, 512, SMEM_TOTAL>>>();
    kred<<<1, 256>>>((float*)d_out);
}

// round 17
// speedup vs baseline: 1.3026x; 1.0163x over previous
#include <cuda_runtime.h>
#include <cuda_bf16.h>
#include <cstdint>

// Problem constants
#define N_TOT 4096
#define D1    4096
#define D2    2048
#define NTI   16            // 256-row blocks
#define NTJ   32            // 128-col blocks
#define NTILES 272          // tiles (I,J) with J >= 2I
#define BK    128           // k-tile (two SW128 half-rows per row)

// SMEM: 2 stages A (2x64KB) | 2 stages B (2x32KB) | reduction scratch
#define SM_ASTAGE 65536
#define SM_BSTAGE 32768
#define SM_B_OFF  131072
#define SM_RED    196608
#define SMEM_TOTAL (196608 + 128)

// ---------------- device scratch ----------------
__device__ __nv_bfloat16 g_t1[(size_t)N_TOT * D1];   // 32 MB
__device__ __nv_bfloat16 g_t2[(size_t)N_TOT * D2];   // 16 MB
__device__ float g_sq1[N_TOT];
__device__ float g_sq2[N_TOT];
__device__ float g_pcs1[(size_t)512 * D1];           // 8 MB
__device__ float g_pcs2[(size_t)512 * D2];           // 4 MB
__device__ float g_c[2];
__device__ float g_partials[NTILES];
__device__ double g_bwp[26];                         // 24 ss partials + ssq1 + ssq2
__device__ int    g_bwc = 0;                         // ticket counter (self-resetting)
__device__ float g_kk[(size_t)NTILES * 32768];       // 35.7 MB k1 scratch

// ---------------- helpers ----------------
__device__ __forceinline__ float ex2f(float x) {
    float y; asm("ex2.approx.ftz.f32 %0, %1;" : "=f"(y) : "f"(x)); return y;
}
// sum_{i=0..4} exp(-t/2^i) = y + y^2 + y^4 + y^8 + y^16, y = exp(-t/16)
__device__ __forceinline__ float kern5b(float l2, float c16) {
    float y = ex2f(-fmaxf(l2, 0.0f) * c16);
    float y2 = y * y, y4 = y2 * y2, y8 = y4 * y4, y16 = y8 * y8;
    return y + y2 + y4 + y8 + y16;
}
__device__ __forceinline__ void cpa16(uint32_t s, const void* g) {
    asm volatile("cp.async.cg.shared.global [%0], [%1], 16;" :: "r"(s), "l"(g));
}
__device__ __forceinline__ void ldsm4(uint32_t* r, uint32_t addr) {
    asm volatile("ldmatrix.sync.aligned.m8n8.x4.shared.b16 {%0,%1,%2,%3}, [%4];"
        : "=r"(r[0]), "=r"(r[1]), "=r"(r[2]), "=r"(r[3]) : "r"(addr));
}
__device__ __forceinline__ void mma16816(float* d, const uint32_t* a, const uint32_t* b) {
    asm volatile(
        "mma.sync.aligned.m16n8k16.row.col.f32.bf16.bf16.f32 "
        "{%0,%1,%2,%3}, {%4,%5,%6,%7}, {%8,%9}, {%0,%1,%2,%3};"
        : "+f"(d[0]), "+f"(d[1]), "+f"(d[2]), "+f"(d[3])
        : "r"(a[0]), "r"(a[1]), "r"(a[2]), "r"(a[3]), "r"(b[0]), "r"(b[1]));
}

// swizzled offset inside a tile with 256B rows (two SW128 half-rows):
// ch = 16B chunk index within the row (0..15)
__device__ __forceinline__ uint32_t sw256(int row, int ch) {
    return (uint32_t)(row * 256 + ((ch >> 3) << 7) + (((ch & 7) ^ (row & 7)) << 4));
}

// ---------------- pre-pass 1: convert + row sq-norms + col partial sums ----------------
// 512 blocks x 512 threads: 8 rows per block
__global__ __launch_bounds__(512) void kprep(
        const float* __restrict__ z1s, const float* __restrict__ z1t,
        const float* __restrict__ z2s, const float* __restrict__ z2t) {
    int bid = blockIdx.x, tid = threadIdx.x;
    int lane = tid & 31, wid = tid >> 5;
    __shared__ float sred1[8][16];
    __shared__ float sred2[8][16];
    float4 ca1[2], ca2;
    ca1[0] = make_float4(0.f, 0.f, 0.f, 0.f);
    ca1[1] = make_float4(0.f, 0.f, 0.f, 0.f);
    ca2 = make_float4(0.f, 0.f, 0.f, 0.f);

    for (int r8 = 0; r8 < 8; r8++) {
        int r = bid * 8 + r8;
        const float4* s1 = (const float4*)((r < 2048) ? z1s + (size_t)r * D1
                                                      : z1t + (size_t)(r - 2048) * D1);
        float sq = 0.0f;
        #pragma unroll
        for (int s = 0; s < 2; s++) {
            float4 v = s1[tid + 512 * s];
            __nv_bfloat162 h0 = {__float2bfloat16(v.x), __float2bfloat16(v.y)};
            __nv_bfloat162 h1 = {__float2bfloat16(v.z), __float2bfloat16(v.w)};
            uint2 pk = {*(uint32_t*)&h0, *(uint32_t*)&h1};
            *(uint2*)(g_t1 + (size_t)r * D1 + 4 * (tid + 512 * s)) = pk;
            sq += v.x * v.x + v.y * v.y + v.z * v.z + v.w * v.w;
            ca1[s].x += v.x; ca1[s].y += v.y; ca1[s].z += v.z; ca1[s].w += v.w;
        }
        #pragma unroll
        for (int o = 16; o; o >>= 1) sq += __shfl_xor_sync(0xffffffffu, sq, o);
        if (lane == 0) sred1[r8][wid] = sq;

        const float4* s2 = (const float4*)((r < 2048) ? z2s + (size_t)r * D2
                                                      : z2t + (size_t)(r - 2048) * D2);
        {
            float4 v = s2[tid];
            __nv_bfloat162 h0 = {__float2bfloat16(v.x), __float2bfloat16(v.y)};
            __nv_bfloat162 h1 = {__float2bfloat16(v.z), __float2bfloat16(v.w)};
            uint2 pk = {*(uint32_t*)&h0, *(uint32_t*)&h1};
            *(uint2*)(g_t2 + (size_t)r * D2 + 4 * tid) = pk;
            float sq2v = v.x * v.x + v.y * v.y + v.z * v.z + v.w * v.w;
            ca2.x += v.x; ca2.y += v.y; ca2.z += v.z; ca2.w += v.w;
            #pragma unroll
            for (int o = 16; o; o >>= 1) sq2v += __shfl_xor_sync(0xffffffffu, sq2v, o);
            if (lane == 0) sred2[r8][wid] = sq2v;
        }
    }
    #pragma unroll
    for (int s = 0; s < 2; s++)
        *(float4*)&g_pcs1[(size_t)bid * D1 + 2048 * s + 4 * tid] = ca1[s];
    *(float4*)&g_pcs2[(size_t)bid * D2 + 4 * tid] = ca2;
    __syncthreads();
    if (tid < 8) {
        float s = 0.0f;
        #pragma unroll
        for (int w = 0; w < 16; w++) s += sred1[tid][w];
        g_sq1[bid * 8 + tid] = s;
    } else if (tid < 16) {
        float s = 0.0f;
        #pragma unroll
        for (int w = 0; w < 16; w++) s += sred2[tid - 8][w];
        g_sq2[bid * 8 + tid - 8] = s;
    }
}

// ---------------- pre-pass 2 (merged): col reduce + bandwidth constants ----------------
// 24 blocks: 0-15 handle D1 columns, 16-23 handle D2 columns. Colsum kept in
// registers; per-block double partials in fixed slots; deterministic last-block
// fixed-order final sum -> g_c. Ticket counter self-resets for graph replay.
__global__ void kbw() {
    int b = blockIdx.x, tid = threadIdx.x;
    __shared__ double sh[256];
    __shared__ double sh2[256];
    __shared__ int s_last;

    double ss = 0.0, extra = 0.0;
    if (b < 16) {
        int j = b * 256 + tid;
        float s = 0.0f;
        for (int k = 0; k < 512; k++) s += g_pcs1[(size_t)k * D1 + j];
        ss = (double)s * (double)s;
        if (b == 0)
            for (int i = tid; i < N_TOT; i += 256) extra += (double)g_sq1[i];
    } else {
        int j = (b - 16) * 256 + tid;
        float s = 0.0f;
        for (int k = 0; k < 512; k++) s += g_pcs2[(size_t)k * D2 + j];
        ss = (double)s * (double)s;
        if (b == 16)
            for (int i = tid; i < N_TOT; i += 256) extra += (double)g_sq2[i];
    }
    sh[tid] = ss; sh2[tid] = extra;
    __syncthreads();
    for (int s = 128; s; s >>= 1) {
        if (tid < s) { sh[tid] += sh[tid + s]; sh2[tid] += sh2[tid + s]; }
        __syncthreads();
    }
    if (tid == 0) {
        g_bwp[b] = sh[0];
        if (b == 0)  g_bwp[24] = sh2[0];
        if (b == 16) g_bwp[25] = sh2[0];
        __threadfence();
        int old = atomicAdd(&g_bwc, 1);
        s_last = (old == 23) ? 1 : 0;
    }
    __syncthreads();
    if (s_last && tid == 0) {
        __threadfence();
        double n = (double)N_TOT;
        double ss1 = 0.0, ss2 = 0.0;
        #pragma unroll
        for (int k = 0; k < 16; k++) ss1 += g_bwp[k];
        #pragma unroll
        for (int k = 16; k < 24; k++) ss2 += g_bwp[k];
        double suml1 = 2.0 * n * g_bwp[24] - 2.0 * ss1;
        double suml2 = 2.0 * n * g_bwp[25] - 2.0 * ss2;
        double bw1 = suml1 / (n * n - n) / 4.0;
        double bw2 = suml2 / (n * n - n) / 4.0;
        g_c[0] = (float)(1.4426950408889634 / bw1);
        g_c[1] = (float)(1.4426950408889634 / bw2);
        g_bwc = 0;                           // reset for next graph replay
    }
}

// ---------------- main fused kernel: 256x128 CTA, BK=128, 2-stage ----------------
__device__ __forceinline__ void load_tiles(uint32_t sb, int stage,
        const __nv_bfloat16* A, const __nv_bfloat16* B, int ld, int k0, int tid) {
    uint32_t sA = sb + (uint32_t)stage * SM_ASTAGE;
    uint32_t sB = sb + SM_B_OFF + (uint32_t)stage * SM_BSTAGE;
    #pragma unroll
    for (int v = 0; v < 8; v++) {               // A: 256 rows x 16 chunks = 4096 x 16B
        int chunk = tid + v * 512;
        int row = chunk >> 4, c = chunk & 15;
        cpa16(sA + sw256(row, c), A + (size_t)row * ld + k0 + c * 8);
    }
    #pragma unroll
    for (int v = 0; v < 4; v++) {               // B: 128 rows x 16 chunks = 2048 x 16B
        int chunk = tid + v * 512;
        int row = chunk >> 4, c = chunk & 15;
        cpa16(sB + sw256(row, c), B + (size_t)row * ld + k0 + c * 8);
    }
}

__device__ __forceinline__ void compute_stage(uint32_t sA, uint32_t sB,
        float acc[4][4][4], int lane, int wm, int wn) {
    #pragma unroll
    for (int s16 = 0; s16 < 8; s16++) {
        uint32_t a[4][4], b[2][4];
        #pragma unroll
        for (int mt = 0; mt < 4; mt++) {
            int row = wm * 64 + mt * 16 + (lane & 15);
            int ch  = 2 * s16 + (lane >> 4);
            ldsm4(a[mt], sA + sw256(row, ch));
        }
        #pragma unroll
        for (int p = 0; p < 2; p++) {
            int g = lane >> 3;
            int row = wn * 32 + p * 16 + ((g >> 1) << 3) + (lane & 7);
            int ch  = 2 * s16 + (g & 1);
            ldsm4(b[p], sB + sw256(row, ch));
        }
        #pragma unroll
        for (int mt = 0; mt < 4; mt++)
            #pragma unroll
            for (int nt = 0; nt < 4; nt++)
                mma16816(acc[mt][nt], a[mt], &b[nt >> 1][(nt & 1) * 2]);
    }
}

__device__ void run_gemm(const __nv_bfloat16* A, const __nv_bfloat16* B, int ld,
        int nsteps, float acc[4][4][4], uint32_t sb, int tid, int lane, int wm, int wn) {
    asm volatile("cp.async.wait_group 0;");     // prior phase fully drained
    __syncthreads();
    load_tiles(sb, 0, A, B, ld, 0, tid);
    asm volatile("cp.async.commit_group;");
    for (int s = 0; s < nsteps; s++) {
        asm volatile("cp.async.wait_group 0;"); // stage s resident
        __syncthreads();                        // also: all warps done with stage s-1
        if (s + 1 < nsteps) {
            load_tiles(sb, (s + 1) & 1, A, B, ld, (s + 1) * BK, tid);
            asm volatile("cp.async.commit_group;");
        }
        compute_stage(sb + (uint32_t)(s & 1) * SM_ASTAGE,
                      sb + SM_B_OFF + (uint32_t)(s & 1) * SM_BSTAGE,
                      acc, lane, wm, wn);
    }
}

__global__ __launch_bounds__(512, 1) void kmain() {
    extern __shared__ __align__(16) char smem[];
    uint32_t sb = (uint32_t)__cvta_generic_to_shared(smem);
    int tid = threadIdx.x, lane = tid & 31, wid = tid >> 5;
    int wm = wid >> 2, wn = wid & 3;    // 4 x 4 warp grid, warp tile 64x32

    // tile mapping: (I,J), I in [0,16), J in [2I, 32)
    int rem = blockIdx.x, I = 0;
    while (rem >= NTJ - 2 * I) { rem -= NTJ - 2 * I; I++; }
    int J = 2 * I + rem;

    float acc[4][4][4];
    #pragma unroll
    for (int mt = 0; mt < 4; mt++)
        #pragma unroll
        for (int nt = 0; nt < 4; nt++)
            #pragma unroll
            for (int r = 0; r < 4; r++) acc[mt][nt][r] = 0.0f;

    // ---- phase 1: G1 over total1 ----
    run_gemm(g_t1 + (size_t)(I * 256) * D1, g_t1 + (size_t)(J * 128) * D1,
             D1, D1 / BK, acc, sb, tid, lane, wm, wn);

    {
        float c116 = g_c[0] * 0.0625f;
        float sqi[4][2], sqj[4][2];
        #pragma unroll
        for (int mt = 0; mt < 4; mt++) {
            int ib = I * 256 + wm * 64 + mt * 16 + (lane >> 2);
            sqi[mt][0] = g_sq1[ib];
            sqi[mt][1] = g_sq1[ib + 8];
        }
        #pragma unroll
        for (int nt = 0; nt < 4; nt++) {
            int jb = J * 128 + wn * 32 + nt * 8 + ((lane & 3) << 1);
            sqj[nt][0] = g_sq1[jb];
            sqj[nt][1] = g_sq1[jb + 1];
        }
        float* kkb = g_kk + (size_t)blockIdx.x * 32768;
        #pragma unroll
        for (int mt = 0; mt < 4; mt++)
            #pragma unroll
            for (int nt = 0; nt < 4; nt++)
                #pragma unroll
                for (int r = 0; r < 4; r++) {
                    float l2 = sqi[mt][r >> 1] + sqj[nt][r & 1] - 2.0f * acc[mt][nt][r];
                    kkb[(mt * 16 + nt * 4 + r) * 512 + tid] = kern5b(l2, c116);
                    acc[mt][nt][r] = 0.0f;
                }
    }

    // ---- phase 2: G2 over total2 ----
    run_gemm(g_t2 + (size_t)(I * 256) * D2, g_t2 + (size_t)(J * 128) * D2,
             D2, D2 / BK, acc, sb, tid, lane, wm, wn);

    float part = 0.0f;
    {
        float c216 = g_c[1] * 0.0625f;
        float sqi[4][2], sqj[4][2];
        #pragma unroll
        for (int mt = 0; mt < 4; mt++) {
            int ib = I * 256 + wm * 64 + mt * 16 + (lane >> 2);
            sqi[mt][0] = g_sq2[ib];
            sqi[mt][1] = g_sq2[ib + 8];
        }
        #pragma unroll
        for (int nt = 0; nt < 4; nt++) {
            int jb = J * 128 + wn * 32 + nt * 8 + ((lane & 3) << 1);
            sqj[nt][0] = g_sq2[jb];
            sqj[nt][1] = g_sq2[jb + 1];
        }
        const float PC = 1.0f / (2048.0f * 2047.0f);
        const float QC = 1.0f / (2048.0f * 2048.0f);
        const float* kkb = g_kk + (size_t)blockIdx.x * 32768;
        #pragma unroll
        for (int mt = 0; mt < 4; mt++)
            #pragma unroll
            for (int nt = 0; nt < 4; nt++)
                #pragma unroll
                for (int r = 0; r < 4; r++) {
                    int i = I * 256 + wm * 64 + mt * 16 + (lane >> 2) + ((r >> 1) << 3);
                    int j = J * 128 + wn * 32 + nt * 8 + ((lane & 3) << 1) + (r & 1);
                    float l2 = sqi[mt][r >> 1] + sqj[nt][r & 1] - 2.0f * acc[mt][nt][r];
                    float k2v = kern5b(l2, c216);
                    // strictly-upper mask, x2 symmetry, +/- index-matrix coefficient
                    float coef = (i < j) ? 2.0f * (((i >> 11) == (j >> 11)) ? PC : -QC)
                                         : 0.0f;
                    part += kkb[(mt * 16 + nt * 4 + r) * 512 + tid] * k2v * coef;
                }
    }

    // deterministic CTA reduction
    #pragma unroll
    for (int o = 16; o; o >>= 1) part += __shfl_xor_sync(0xffffffffu, part, o);
    float* red = (float*)(smem + SM_RED);
    __syncthreads();
    if (lane == 0) red[wid] = part;
    __syncthreads();
    if (tid == 0) {
        float s = 0.0f;
        #pragma unroll
        for (int w = 0; w < 16; w++) s += red[w];
        g_partials[blockIdx.x] = s;
    }
}

// ---------------- final deterministic reduction ----------------
__global__ void kred(float* out) {
    int tid = threadIdx.x;
    __shared__ double sh[256];
    double a = 0.0;
    for (int i = tid; i < NTILES; i += 256) a += (double)g_partials[i];
    sh[tid] = a; __syncthreads();
    for (int s = 128; s; s >>= 1) { if (tid < s) sh[tid] += sh[tid + s]; __syncthreads(); }
    if (tid == 0) out[0] = (float)(sh[0] + 2.0 / 2047.0);
}

// ---------------- launch ----------------
extern "C" void kernel_launch(void* const* d_in, const int* in_sizes, int n_in,
                              void* d_out, int out_size) {
    const float* z1s = (const float*)d_in[0];
    const float* z1t = (const float*)d_in[1];
    const float* z2s = (const float*)d_in[2];
    const float* z2t = (const float*)d_in[3];

    cudaFuncSetAttribute(kmain, cudaFuncAttributeMaxDynamicSharedMemorySize, SMEM_TOTAL);

    kprep<<<512, 512>>>(z1s, z1t, z2s, z2t);
    kbw<<<24, 256>>>();
    kmain<<<NTILES, 512, SMEM_TOTAL>>>();
    kred<<<1, 256>>>((float*)d_out);
}